// round 1
// baseline (speedup 1.0000x reference)
#include <cuda_runtime.h>
#include <cuda_bf16.h>
#include <math.h>

// ---------------------------------------------------------------------------
// Problem constants
// B=8, C=128, H=W=64, L=4096, M=B*L=32768
// branch dim Cb=64, heads/branch=4, head dim d=16, split size=8
// ---------------------------------------------------------------------------
#define M_ROWS   32768
#define C_DIM    128
#define L_DIM    4096
#define B_DIM    8
#define HID      512
#define QKV_N    384
#define ZC       512

// ---------------------------------------------------------------------------
// Scratch buffers (device globals -- no allocation allowed)
// ---------------------------------------------------------------------------
__device__ __align__(16) float g_xf [M_ROWS * C_DIM];
__device__ __align__(16) float g_h1 [M_ROWS * C_DIM];
__device__ __align__(16) float g_qkv[M_ROWS * QKV_N];
__device__ __align__(16) float g_att[M_ROWS * C_DIM];
__device__ __align__(16) float g_xf2[M_ROWS * C_DIM];
__device__ __align__(16) float g_h2 [M_ROWS * C_DIM];
__device__ __align__(16) float g_mid[M_ROWS * HID];
__device__ __align__(16) float g_y  [M_ROWS * C_DIM];
__device__ __align__(16) float g_z1 [B_DIM * C_DIM];
__device__ __align__(16) float g_z2 [B_DIM * C_DIM];

// ---------------------------------------------------------------------------
// z projections: z1[b][c] = dot(z[b,:], Wz1[c,:]), same for z2.  Tiny.
// ---------------------------------------------------------------------------
__global__ void zproj_kernel(const float* __restrict__ z,
                             const float* __restrict__ Wz1,
                             const float* __restrict__ Wz2) {
    int o = blockIdx.x * 256 + threadIdx.x;      // 0..2047
    if (o >= 2048) return;
    int which = o >> 10;
    int b = (o >> 7) & 7;
    int c = o & 127;
    const float* W = (which ? Wz2 : Wz1) + c * ZC;
    const float* zb = z + b * ZC;
    float s = 0.f;
    #pragma unroll 8
    for (int k = 0; k < ZC; k++) s += zb[k] * W[k];
    (which ? g_z2 : g_z1)[b * C_DIM + c] = s;
}

// ---------------------------------------------------------------------------
// Transpose x (B,C,HW) -> xf (B,L,C)   +   h1 = LN(xf)*g+b + z1[b]
// block: (l-tile of 32, batch) , 256 threads
// ---------------------------------------------------------------------------
__global__ void __launch_bounds__(256) ln1_kernel(const float* __restrict__ x,
                                                  const float* __restrict__ gamma,
                                                  const float* __restrict__ beta) {
    __shared__ float sm[128][33];
    int b  = blockIdx.y;
    int l0 = blockIdx.x * 32;
    int tid = threadIdx.x;
    const float* xb = x + (size_t)b * C_DIM * L_DIM;

    #pragma unroll
    for (int r = 0; r < 16; r++) {
        int c = r * 8 + (tid >> 5);
        int j = tid & 31;
        sm[c][j] = xb[(size_t)c * L_DIM + l0 + j];
    }
    __syncthreads();

    int warp = tid >> 5, lane = tid & 31;
    #pragma unroll
    for (int rr = 0; rr < 4; rr++) {
        int j = warp + rr * 8;
        float v[4];
        float s = 0.f, s2 = 0.f;
        #pragma unroll
        for (int u = 0; u < 4; u++) {
            v[u] = sm[lane + 32 * u][j];
            s += v[u]; s2 += v[u] * v[u];
        }
        #pragma unroll
        for (int o = 16; o; o >>= 1) {
            s  += __shfl_xor_sync(0xffffffffu, s,  o);
            s2 += __shfl_xor_sync(0xffffffffu, s2, o);
        }
        float mu   = s  * (1.f / 128.f);
        float var  = s2 * (1.f / 128.f) - mu * mu;
        float rstd = rsqrtf(var + 1e-5f);
        int l = l0 + j;
        size_t row = ((size_t)b * L_DIM + l) * C_DIM;
        #pragma unroll
        for (int u = 0; u < 4; u++) {
            int c = lane + 32 * u;
            g_xf[row + c] = v[u];
            g_h1[row + c] = (v[u] - mu) * rstd * gamma[c] + beta[c]
                          + g_z1[b * C_DIM + c];
        }
    }
}

// ---------------------------------------------------------------------------
// LN2: h2 = LN(xf2)*g+b + z2[b].   1 warp per row.
// ---------------------------------------------------------------------------
__global__ void __launch_bounds__(256) ln2_kernel(const float* __restrict__ gamma,
                                                  const float* __restrict__ beta) {
    int row  = blockIdx.x * 8 + (threadIdx.x >> 5);
    int lane = threadIdx.x & 31;
    int b = row >> 12;
    const float* xr = g_xf2 + (size_t)row * C_DIM;
    float v[4]; float s = 0.f, s2 = 0.f;
    #pragma unroll
    for (int u = 0; u < 4; u++) {
        v[u] = xr[lane + 32 * u];
        s += v[u]; s2 += v[u] * v[u];
    }
    #pragma unroll
    for (int o = 16; o; o >>= 1) {
        s  += __shfl_xor_sync(0xffffffffu, s,  o);
        s2 += __shfl_xor_sync(0xffffffffu, s2, o);
    }
    float mu   = s  * (1.f / 128.f);
    float var  = s2 * (1.f / 128.f) - mu * mu;
    float rstd = rsqrtf(var + 1e-5f);
    float* hr = g_h2 + (size_t)row * C_DIM;
    #pragma unroll
    for (int u = 0; u < 4; u++) {
        int c = lane + 32 * u;
        hr[c] = (v[u] - mu) * rstd * gamma[c] + beta[c] + g_z2[b * C_DIM + c];
    }
}

// ---------------------------------------------------------------------------
// GEMM: C[m,n] = act( res[m,n] + bias[n] + sum_k A[m,k]*W[n,k] )
// A row-major (M,K); W row-major (N,K).  BM=BN=128, BK=16, 8x8 per thread.
// M % 128 == 0, N % 128 == 0, K % 16 == 0 for all call sites.
// ---------------------------------------------------------------------------
#define BM 128
#define BN 128
#define BKC 16
__global__ void __launch_bounds__(256) gemm_kernel(
        const float* __restrict__ A, const float* __restrict__ W,
        const float* __restrict__ bias, const float* __restrict__ res,
        float* __restrict__ C, int M, int N, int K, int act) {
    __shared__ float As[BKC][BM + 4];
    __shared__ float Bs[BKC][BN + 4];
    int tid = threadIdx.x;
    int tx = tid & 15, ty = tid >> 4;
    int m0 = blockIdx.y * BM, n0 = blockIdx.x * BN;

    float acc[8][8];
    #pragma unroll
    for (int i = 0; i < 8; i++)
        #pragma unroll
        for (int j = 0; j < 8; j++) acc[i][j] = 0.f;

    for (int k0 = 0; k0 < K; k0 += BKC) {
        #pragma unroll
        for (int r = 0; r < 2; r++) {
            int i = tid + 256 * r;          // 0..511
            int row = i >> 2;               // 0..127
            int kc = (i & 3) << 2;          // 0,4,8,12
            float4 va = *(const float4*)&A[(size_t)(m0 + row) * K + k0 + kc];
            As[kc + 0][row] = va.x; As[kc + 1][row] = va.y;
            As[kc + 2][row] = va.z; As[kc + 3][row] = va.w;
            float4 vb = *(const float4*)&W[(size_t)(n0 + row) * K + k0 + kc];
            Bs[kc + 0][row] = vb.x; Bs[kc + 1][row] = vb.y;
            Bs[kc + 2][row] = vb.z; Bs[kc + 3][row] = vb.w;
        }
        __syncthreads();
        #pragma unroll
        for (int kk = 0; kk < BKC; kk++) {
            float a[8], bv[8];
            *(float4*)&a[0]  = *(const float4*)&As[kk][ty * 8];
            *(float4*)&a[4]  = *(const float4*)&As[kk][ty * 8 + 4];
            *(float4*)&bv[0] = *(const float4*)&Bs[kk][tx * 8];
            *(float4*)&bv[4] = *(const float4*)&Bs[kk][tx * 8 + 4];
            #pragma unroll
            for (int i = 0; i < 8; i++)
                #pragma unroll
                for (int j = 0; j < 8; j++)
                    acc[i][j] = fmaf(a[i], bv[j], acc[i][j]);
        }
        __syncthreads();
    }

    #pragma unroll
    for (int i = 0; i < 8; i++) {
        int m = m0 + ty * 8 + i;
        #pragma unroll
        for (int j = 0; j < 8; j++) {
            int n = n0 + tx * 8 + j;
            float v = acc[i][j];
            if (bias) v += bias[n];
            if (res)  v += res[(size_t)m * N + n];
            if (act)  v = 0.5f * v * (1.f + erff(v * 0.70710678118654752f));
            C[(size_t)m * N + n] = v;
        }
    }
}

// ---------------------------------------------------------------------------
// Windowed attention + LePE.  One block per (window, head, branch).
// br0: H_sp=64, W_sp=8, l = h*64 + wn*8 + w,  n = h*8  + w
// br1: H_sp=8,  W_sp=64, l = wn*512 + n,      n = h*64 + w
// Q/K/V smem layout [16][513] (pad kills bank conflicts), P per warp [512].
// ---------------------------------------------------------------------------
#define QKV_STRIDE 513
__device__ __forceinline__ int tok_to_l(int n, int br, int wn) {
    if (br == 0) { int h = n >> 3, w = n & 7; return h * 64 + wn * 8 + w; }
    return wn * 512 + n;
}

__global__ void __launch_bounds__(256) attn_kernel(
        const float* __restrict__ lepe_w0, const float* __restrict__ lepe_b0,
        const float* __restrict__ lepe_w1, const float* __restrict__ lepe_b1) {
    extern __shared__ float smf[];
    float* Qs  = smf;                        // 16*513
    float* Ks  = Qs + 16 * QKV_STRIDE;
    float* Vs  = Ks + 16 * QKV_STRIDE;
    float* Ps  = Vs + 16 * QKV_STRIDE;       // 8*512
    float* wsm = Ps + 8 * 512;               // 16*9
    float* bsm = wsm + 144;                  // 16

    int wglob = blockIdx.x;                  // 0..63
    int hd    = blockIdx.y;                  // 0..3
    int br    = blockIdx.z;                  // 0..1
    int b  = wglob >> 3;
    int wn = wglob & 7;
    int cb = br * 64 + hd * 16;
    int tid = threadIdx.x;

    // load Q/K/V tiles (512 tokens x 16 dims each)
    for (int t = tid; t < 512; t += 256) {
        int l = tok_to_l(t, br, wn);
        const float* base = g_qkv + ((size_t)(b * L_DIM + l)) * QKV_N + cb;
        #pragma unroll
        for (int part = 0; part < 3; part++) {
            const float4* p = (const float4*)(base + part * 128);
            float* dst = (part == 0) ? Qs : (part == 1) ? Ks : Vs;
            float4 v0 = p[0], v1 = p[1], v2 = p[2], v3 = p[3];
            dst[ 0*QKV_STRIDE + t] = v0.x; dst[ 1*QKV_STRIDE + t] = v0.y;
            dst[ 2*QKV_STRIDE + t] = v0.z; dst[ 3*QKV_STRIDE + t] = v0.w;
            dst[ 4*QKV_STRIDE + t] = v1.x; dst[ 5*QKV_STRIDE + t] = v1.y;
            dst[ 6*QKV_STRIDE + t] = v1.z; dst[ 7*QKV_STRIDE + t] = v1.w;
            dst[ 8*QKV_STRIDE + t] = v2.x; dst[ 9*QKV_STRIDE + t] = v2.y;
            dst[10*QKV_STRIDE + t] = v2.z; dst[11*QKV_STRIDE + t] = v2.w;
            dst[12*QKV_STRIDE + t] = v3.x; dst[13*QKV_STRIDE + t] = v3.y;
            dst[14*QKV_STRIDE + t] = v3.z; dst[15*QKV_STRIDE + t] = v3.w;
        }
    }
    const float* lw = br ? lepe_w1 : lepe_w0;
    const float* lb = br ? lepe_b1 : lepe_b0;
    if (tid < 144) wsm[tid] = lw[hd * 16 * 9 + tid];
    if (tid < 16)  bsm[tid] = lb[hd * 16 + tid];
    __syncthreads();

    int warp = tid >> 5, lane = tid & 31;
    const int HS = br ? 8 : 64;
    const int WS = br ? 64 : 8;
    float* Pw = Ps + (warp << 9);

    for (int nq = warp; nq < 512; nq += 8) {
        // q vector (broadcast loads), scaled at score time
        float qv[16];
        #pragma unroll
        for (int dd = 0; dd < 16; dd++) qv[dd] = Qs[dd * QKV_STRIDE + nq];

        // scores: each lane owns keys lane, lane+32, ...
        float s[16];
        #pragma unroll
        for (int kk = 0; kk < 16; kk++) {
            int key = lane + (kk << 5);
            float a = 0.f;
            #pragma unroll
            for (int dd = 0; dd < 16; dd++)
                a = fmaf(qv[dd], Ks[dd * QKV_STRIDE + key], a);
            s[kk] = a * 0.25f;                     // d^-0.5, d=16
        }
        // softmax
        float mx = s[0];
        #pragma unroll
        for (int kk = 1; kk < 16; kk++) mx = fmaxf(mx, s[kk]);
        #pragma unroll
        for (int o = 16; o; o >>= 1) mx = fmaxf(mx, __shfl_xor_sync(0xffffffffu, mx, o));
        float sum = 0.f;
        #pragma unroll
        for (int kk = 0; kk < 16; kk++) { s[kk] = __expf(s[kk] - mx); sum += s[kk]; }
        #pragma unroll
        for (int o = 16; o; o >>= 1) sum += __shfl_xor_sync(0xffffffffu, sum, o);
        float inv = 1.f / sum;
        #pragma unroll
        for (int kk = 0; kk < 16; kk++) Pw[lane + (kk << 5)] = s[kk] * inv;
        __syncwarp();

        // PV: lane = 2*dd + half; each half covers 256 keys (rotated to
        // keep Vs accesses conflict-free: 256 ≡ 0 mod 32 banks otherwise)
        int dd   = lane >> 1;
        int half = lane & 1;
        float oacc = 0.f;
        const float* vrow = Vs + dd * QKV_STRIDE + (half << 8);
        const float* prow = Pw + (half << 8);
        #pragma unroll 4
        for (int jj = 0; jj < 256; jj++) {
            int j = (jj + (half << 4)) & 255;
            oacc = fmaf(prow[j], vrow[j], oacc);
        }
        oacc += __shfl_xor_sync(0xffffffffu, oacc, 1);

        if (half == 0) {
            // LePE: 3x3 depthwise conv of (unscaled) q window image, SAME pad
            int h = nq / WS, w = nq % WS;
            float lep = bsm[dd];
            #pragma unroll
            for (int ky = 0; ky < 3; ky++) {
                int hh = h + ky - 1;
                if (hh < 0 || hh >= HS) continue;
                #pragma unroll
                for (int kx = 0; kx < 3; kx++) {
                    int ww = w + kx - 1;
                    if (ww < 0 || ww >= WS) continue;
                    lep = fmaf(wsm[dd * 9 + ky * 3 + kx],
                               Qs[dd * QKV_STRIDE + hh * WS + ww], lep);
                }
            }
            int l = tok_to_l(nq, br, wn);
            g_att[((size_t)(b * L_DIM) + l) * C_DIM + cb + dd] = oacc + lep;
        }
        __syncwarp();
    }
}

// ---------------------------------------------------------------------------
// y (B,L,C) -> out (B,C,H,W)
// ---------------------------------------------------------------------------
__global__ void __launch_bounds__(256) out_transpose_kernel(float* __restrict__ out) {
    __shared__ float sm[128][33];
    int b  = blockIdx.y;
    int l0 = blockIdx.x * 32;
    int tid = threadIdx.x;
    const float* yb = g_y + ((size_t)b * L_DIM + l0) * C_DIM;
    #pragma unroll
    for (int r = 0; r < 16; r++) {
        int i = r * 256 + tid;
        int lloc = i >> 7, c = i & 127;
        sm[c][lloc] = yb[(size_t)lloc * C_DIM + c];
    }
    __syncthreads();
    #pragma unroll
    for (int r = 0; r < 16; r++) {
        int c = r * 8 + (tid >> 5);
        int j = tid & 31;
        out[(size_t)b * C_DIM * L_DIM + (size_t)c * L_DIM + l0 + j] = sm[c][j];
    }
}

// ---------------------------------------------------------------------------
// launch
// ---------------------------------------------------------------------------
extern "C" void kernel_launch(void* const* d_in, const int* in_sizes, int n_in,
                              void* d_out, int out_size) {
    const float* x       = (const float*)d_in[0];
    const float* z       = (const float*)d_in[1];
    const float* ln1_g   = (const float*)d_in[2];
    const float* ln1_b   = (const float*)d_in[3];
    const float* ln2_g   = (const float*)d_in[4];
    const float* ln2_b   = (const float*)d_in[5];
    const float* Wz1     = (const float*)d_in[6];
    const float* Wz2     = (const float*)d_in[7];
    const float* Wqkv    = (const float*)d_in[8];
    const float* Wproj   = (const float*)d_in[9];
    const float* bproj   = (const float*)d_in[10];
    const float* lepe_w0 = (const float*)d_in[11];
    const float* lepe_b0 = (const float*)d_in[12];
    const float* lepe_w1 = (const float*)d_in[13];
    const float* lepe_b1 = (const float*)d_in[14];
    const float* W1      = (const float*)d_in[15];
    const float* b1      = (const float*)d_in[16];
    const float* W2      = (const float*)d_in[17];
    const float* b2      = (const float*)d_in[18];
    float* out = (float*)d_out;

    float* p_xf;  cudaGetSymbolAddress((void**)&p_xf,  g_xf);
    float* p_h1;  cudaGetSymbolAddress((void**)&p_h1,  g_h1);
    float* p_qkv; cudaGetSymbolAddress((void**)&p_qkv, g_qkv);
    float* p_att; cudaGetSymbolAddress((void**)&p_att, g_att);
    float* p_xf2; cudaGetSymbolAddress((void**)&p_xf2, g_xf2);
    float* p_h2;  cudaGetSymbolAddress((void**)&p_h2,  g_h2);
    float* p_mid; cudaGetSymbolAddress((void**)&p_mid, g_mid);
    float* p_y;   cudaGetSymbolAddress((void**)&p_y,   g_y);

    const int attn_smem = (3 * 16 * QKV_STRIDE + 8 * 512 + 144 + 16) * (int)sizeof(float);
    cudaFuncSetAttribute(attn_kernel, cudaFuncAttributeMaxDynamicSharedMemorySize, attn_smem);

    // 1) z projections
    zproj_kernel<<<8, 256>>>(z, Wz1, Wz2);
    // 2) transpose + LN1 (+z1)
    ln1_kernel<<<dim3(128, 8), 256>>>(x, ln1_g, ln1_b);
    // 3) qkv = h1 @ Wqkv^T
    gemm_kernel<<<dim3(QKV_N / BN, M_ROWS / BM), 256>>>(
        p_h1, Wqkv, nullptr, nullptr, p_qkv, M_ROWS, QKV_N, C_DIM, 0);
    // 4) windowed attention + LePE (both branches)
    attn_kernel<<<dim3(64, 4, 2), 256, attn_smem>>>(lepe_w0, lepe_b0, lepe_w1, lepe_b1);
    // 5) xf2 = xf + att @ Wproj^T + bproj
    gemm_kernel<<<dim3(C_DIM / BN, M_ROWS / BM), 256>>>(
        p_att, Wproj, bproj, p_xf, p_xf2, M_ROWS, C_DIM, C_DIM, 0);
    // 6) LN2 (+z2)
    ln2_kernel<<<M_ROWS / 8, 256>>>(ln2_g, ln2_b);
    // 7) mid = gelu(h2 @ W1^T + b1)
    gemm_kernel<<<dim3(HID / BN, M_ROWS / BM), 256>>>(
        p_h2, W1, b1, nullptr, p_mid, M_ROWS, HID, C_DIM, 1);
    // 8) y = xf2 + mid @ W2^T + b2
    gemm_kernel<<<dim3(C_DIM / BN, M_ROWS / BM), 256>>>(
        p_mid, W2, b2, p_xf2, p_y, M_ROWS, C_DIM, HID, 0);
    // 9) transpose to (B,C,H,W)
    out_transpose_kernel<<<dim3(128, 8), 256>>>(out);
}

// round 3
// speedup vs baseline: 1.7207x; 1.7207x over previous
#include <cuda_runtime.h>
#include <cuda_bf16.h>
#include <math.h>

// ---------------------------------------------------------------------------
// Problem constants
// ---------------------------------------------------------------------------
#define M_ROWS   32768
#define C_DIM    128
#define L_DIM    4096
#define B_DIM    8
#define HID      512
#define QKV_N    384
#define ZC       512

// ---------------------------------------------------------------------------
// Scratch buffers
// ---------------------------------------------------------------------------
__device__ __align__(16) float g_xf [M_ROWS * C_DIM];
__device__ __align__(16) float g_h1 [M_ROWS * C_DIM];
__device__ __align__(16) float g_qkv[M_ROWS * QKV_N];
__device__ __align__(16) float g_att[M_ROWS * C_DIM];
__device__ __align__(16) float g_xf2[M_ROWS * C_DIM];
__device__ __align__(16) float g_h2 [M_ROWS * C_DIM];
__device__ __align__(16) float g_mid[M_ROWS * HID];
__device__ __align__(16) float g_y  [M_ROWS * C_DIM];
__device__ __align__(16) float g_z1 [B_DIM * C_DIM];
__device__ __align__(16) float g_z2 [B_DIM * C_DIM];

// ---------------------------------------------------------------------------
__global__ void zproj_kernel(const float* __restrict__ z,
                             const float* __restrict__ Wz1,
                             const float* __restrict__ Wz2) {
    int o = blockIdx.x * 256 + threadIdx.x;
    if (o >= 2048) return;
    int which = o >> 10;
    int b = (o >> 7) & 7;
    int c = o & 127;
    const float* W = (which ? Wz2 : Wz1) + c * ZC;
    const float* zb = z + b * ZC;
    float s = 0.f;
    #pragma unroll 8
    for (int k = 0; k < ZC; k++) s += zb[k] * W[k];
    (which ? g_z2 : g_z1)[b * C_DIM + c] = s;
}

// ---------------------------------------------------------------------------
__global__ void __launch_bounds__(256) ln1_kernel(const float* __restrict__ x,
                                                  const float* __restrict__ gamma,
                                                  const float* __restrict__ beta) {
    __shared__ float sm[128][33];
    int b  = blockIdx.y;
    int l0 = blockIdx.x * 32;
    int tid = threadIdx.x;
    const float* xb = x + (size_t)b * C_DIM * L_DIM;
    #pragma unroll
    for (int r = 0; r < 16; r++) {
        int c = r * 8 + (tid >> 5);
        int j = tid & 31;
        sm[c][j] = xb[(size_t)c * L_DIM + l0 + j];
    }
    __syncthreads();
    int warp = tid >> 5, lane = tid & 31;
    #pragma unroll
    for (int rr = 0; rr < 4; rr++) {
        int j = warp + rr * 8;
        float v[4];
        float s = 0.f, s2 = 0.f;
        #pragma unroll
        for (int u = 0; u < 4; u++) {
            v[u] = sm[lane + 32 * u][j];
            s += v[u]; s2 += v[u] * v[u];
        }
        #pragma unroll
        for (int o = 16; o; o >>= 1) {
            s  += __shfl_xor_sync(0xffffffffu, s,  o);
            s2 += __shfl_xor_sync(0xffffffffu, s2, o);
        }
        float mu   = s  * (1.f / 128.f);
        float var  = s2 * (1.f / 128.f) - mu * mu;
        float rstd = rsqrtf(var + 1e-5f);
        int l = l0 + j;
        size_t row = ((size_t)b * L_DIM + l) * C_DIM;
        #pragma unroll
        for (int u = 0; u < 4; u++) {
            int c = lane + 32 * u;
            g_xf[row + c] = v[u];
            g_h1[row + c] = (v[u] - mu) * rstd * gamma[c] + beta[c]
                          + g_z1[b * C_DIM + c];
        }
    }
}

// ---------------------------------------------------------------------------
__global__ void __launch_bounds__(256) ln2_kernel(const float* __restrict__ gamma,
                                                  const float* __restrict__ beta) {
    int row  = blockIdx.x * 8 + (threadIdx.x >> 5);
    int lane = threadIdx.x & 31;
    int b = row >> 12;
    const float* xr = g_xf2 + (size_t)row * C_DIM;
    float v[4]; float s = 0.f, s2 = 0.f;
    #pragma unroll
    for (int u = 0; u < 4; u++) {
        v[u] = xr[lane + 32 * u];
        s += v[u]; s2 += v[u] * v[u];
    }
    #pragma unroll
    for (int o = 16; o; o >>= 1) {
        s  += __shfl_xor_sync(0xffffffffu, s,  o);
        s2 += __shfl_xor_sync(0xffffffffu, s2, o);
    }
    float mu   = s  * (1.f / 128.f);
    float var  = s2 * (1.f / 128.f) - mu * mu;
    float rstd = rsqrtf(var + 1e-5f);
    float* hr = g_h2 + (size_t)row * C_DIM;
    #pragma unroll
    for (int u = 0; u < 4; u++) {
        int c = lane + 32 * u;
        hr[c] = (v[u] - mu) * rstd * gamma[c] + beta[c] + g_z2[b * C_DIM + c];
    }
}

// ---------------------------------------------------------------------------
// GEMM (unchanged)
// ---------------------------------------------------------------------------
#define BM 128
#define BN 128
#define BKC 16
__global__ void __launch_bounds__(256) gemm_kernel(
        const float* __restrict__ A, const float* __restrict__ W,
        const float* __restrict__ bias, const float* __restrict__ res,
        float* __restrict__ C, int M, int N, int K, int act) {
    __shared__ float As[BKC][BM + 4];
    __shared__ float Bs[BKC][BN + 4];
    int tid = threadIdx.x;
    int tx = tid & 15, ty = tid >> 4;
    int m0 = blockIdx.y * BM, n0 = blockIdx.x * BN;

    float acc[8][8];
    #pragma unroll
    for (int i = 0; i < 8; i++)
        #pragma unroll
        for (int j = 0; j < 8; j++) acc[i][j] = 0.f;

    for (int k0 = 0; k0 < K; k0 += BKC) {
        #pragma unroll
        for (int r = 0; r < 2; r++) {
            int i = tid + 256 * r;
            int row = i >> 2;
            int kc = (i & 3) << 2;
            float4 va = *(const float4*)&A[(size_t)(m0 + row) * K + k0 + kc];
            As[kc + 0][row] = va.x; As[kc + 1][row] = va.y;
            As[kc + 2][row] = va.z; As[kc + 3][row] = va.w;
            float4 vb = *(const float4*)&W[(size_t)(n0 + row) * K + k0 + kc];
            Bs[kc + 0][row] = vb.x; Bs[kc + 1][row] = vb.y;
            Bs[kc + 2][row] = vb.z; Bs[kc + 3][row] = vb.w;
        }
        __syncthreads();
        #pragma unroll
        for (int kk = 0; kk < BKC; kk++) {
            float a[8], bv[8];
            *(float4*)&a[0]  = *(const float4*)&As[kk][ty * 8];
            *(float4*)&a[4]  = *(const float4*)&As[kk][ty * 8 + 4];
            *(float4*)&bv[0] = *(const float4*)&Bs[kk][tx * 8];
            *(float4*)&bv[4] = *(const float4*)&Bs[kk][tx * 8 + 4];
            #pragma unroll
            for (int i = 0; i < 8; i++)
                #pragma unroll
                for (int j = 0; j < 8; j++)
                    acc[i][j] = fmaf(a[i], bv[j], acc[i][j]);
        }
        __syncthreads();
    }

    #pragma unroll
    for (int i = 0; i < 8; i++) {
        int m = m0 + ty * 8 + i;
        #pragma unroll
        for (int j = 0; j < 8; j++) {
            int n = n0 + tx * 8 + j;
            float v = acc[i][j];
            if (bias) v += bias[n];
            if (res)  v += res[(size_t)m * N + n];
            if (act)  v = 0.5f * v * (1.f + erff(v * 0.70710678118654752f));
            C[(size_t)m * N + n] = v;
        }
    }
}

// ---------------------------------------------------------------------------
// Register-tiled windowed attention + LePE.
// One block per (window, head, branch). 256 threads, 8 warps.
// Pitches: QP=520 (Q/K transposed), VP=20 (V rows), SP=524 (scores),
//          OPP=18 (partial outputs, scalar/float2 only).
// All vector smem accesses land on pitches that are multiples of 4 floats.
// ---------------------------------------------------------------------------
#define QP 520
#define VP 20
#define SP 524
#define OPP 18
#define OFF_QT 0
#define OFF_KT (16*QP)
#define OFF_V  (2*16*QP)
#define OFF_SS (OFF_V + 512*VP)
#define OFF_OP (OFF_SS + 32*SP)
#define OFF_W  (OFF_OP + 8*32*OPP)
#define OFF_B  (OFF_W + 144)
#define ATTN_SMEM_FLOATS (OFF_B + 16)

__device__ __forceinline__ int tok_to_l(int n, int br, int wn) {
    if (br == 0) { int h = n >> 3, w = n & 7; return h * 64 + wn * 8 + w; }
    return wn * 512 + n;
}

__global__ void __launch_bounds__(256) attn_kernel(
        const float* __restrict__ lepe_w0, const float* __restrict__ lepe_b0,
        const float* __restrict__ lepe_w1, const float* __restrict__ lepe_b1) {
    extern __shared__ float smf[];
    float* Qt = smf + OFF_QT;
    float* Kt = smf + OFF_KT;
    float* Vs = smf + OFF_V;
    float* Ss = smf + OFF_SS;
    float* Op = smf + OFF_OP;
    float* wsm = smf + OFF_W;
    float* bsm = smf + OFF_B;

    int wglob = blockIdx.x;
    int hd    = blockIdx.y;
    int br    = blockIdx.z;
    int b  = wglob >> 3;
    int wn = wglob & 7;
    int cb = br * 64 + hd * 16;
    int tid  = threadIdx.x;
    int warp = tid >> 5, lane = tid & 31;

    // ---- load Q,K (transposed) and V (row-major) ----
    for (int t = tid; t < 512; t += 256) {
        int l = tok_to_l(t, br, wn);
        const float* base = g_qkv + ((size_t)(b * L_DIM + l)) * QKV_N + cb;
        float4 q0 = ((const float4*)base)[0], q1 = ((const float4*)base)[1];
        float4 q2 = ((const float4*)base)[2], q3 = ((const float4*)base)[3];
        Qt[ 0*QP+t]=q0.x; Qt[ 1*QP+t]=q0.y; Qt[ 2*QP+t]=q0.z; Qt[ 3*QP+t]=q0.w;
        Qt[ 4*QP+t]=q1.x; Qt[ 5*QP+t]=q1.y; Qt[ 6*QP+t]=q1.z; Qt[ 7*QP+t]=q1.w;
        Qt[ 8*QP+t]=q2.x; Qt[ 9*QP+t]=q2.y; Qt[10*QP+t]=q2.z; Qt[11*QP+t]=q2.w;
        Qt[12*QP+t]=q3.x; Qt[13*QP+t]=q3.y; Qt[14*QP+t]=q3.z; Qt[15*QP+t]=q3.w;
        const float4* kp = (const float4*)(base + 128);
        float4 k0 = kp[0], k1 = kp[1], k2 = kp[2], k3 = kp[3];
        Kt[ 0*QP+t]=k0.x; Kt[ 1*QP+t]=k0.y; Kt[ 2*QP+t]=k0.z; Kt[ 3*QP+t]=k0.w;
        Kt[ 4*QP+t]=k1.x; Kt[ 5*QP+t]=k1.y; Kt[ 6*QP+t]=k1.z; Kt[ 7*QP+t]=k1.w;
        Kt[ 8*QP+t]=k2.x; Kt[ 9*QP+t]=k2.y; Kt[10*QP+t]=k2.z; Kt[11*QP+t]=k2.w;
        Kt[12*QP+t]=k3.x; Kt[13*QP+t]=k3.y; Kt[14*QP+t]=k3.z; Kt[15*QP+t]=k3.w;
        const float4* vp = (const float4*)(base + 256);
        float4* vdst = (float4*)&Vs[t * VP];        // VP=20 -> 80B, 16B aligned
        vdst[0] = vp[0]; vdst[1] = vp[1]; vdst[2] = vp[2]; vdst[3] = vp[3];
    }
    const float* lw = br ? lepe_w1 : lepe_w0;
    const float* lb = br ? lepe_b1 : lepe_b0;
    if (tid < 144) wsm[tid] = lw[hd * 16 * 9 + tid];
    if (tid < 16)  bsm[tid] = lb[hd * 16 + tid];
    __syncthreads();

    const int HS = br ? 8 : 64;
    const int WS = br ? 64 : 8;

    #pragma unroll 1
    for (int pass = 0; pass < 16; pass++) {
        int qb = pass * 32;

        // ---------- phase 1: S = Q K^T (warp owns keys [64w, 64w+64)) ----------
        {
            int qg = lane >> 2;           // 0..7 -> 4 queries each
            int kg = lane & 3;            // 0..3 -> 4-key strips
            int kbase = warp * 64;
            const float* qa = Qt + qb + qg * 4;
            const float* ka = Kt + kbase + kg * 4;
            float acc[4][16];
            #pragma unroll
            for (int i = 0; i < 4; i++)
                #pragma unroll
                for (int j = 0; j < 16; j++) acc[i][j] = 0.f;
            #pragma unroll 4
            for (int d = 0; d < 16; d++) {
                float a[4], bx[16];
                *(float4*)a = *(const float4*)(qa + d * QP);
                *(float4*)&bx[ 0] = *(const float4*)(ka + d * QP);
                *(float4*)&bx[ 4] = *(const float4*)(ka + d * QP + 16);
                *(float4*)&bx[ 8] = *(const float4*)(ka + d * QP + 32);
                *(float4*)&bx[12] = *(const float4*)(ka + d * QP + 48);
                #pragma unroll
                for (int i = 0; i < 4; i++)
                    #pragma unroll
                    for (int j = 0; j < 16; j++)
                        acc[i][j] = fmaf(a[i], bx[j], acc[i][j]);
            }
            #pragma unroll
            for (int i = 0; i < 4; i++) {
                float* srow = Ss + (qg * 4 + i) * SP + kbase + kg * 4;
                #pragma unroll
                for (int j = 0; j < 4; j++)
                    *(float4*)(srow + 16 * j) = *(float4*)&acc[i][4 * j];
            }
        }
        __syncthreads();

        // ---------- phase 2: softmax rows (scale 0.25) ----------
        {
            #pragma unroll
            for (int rr = 0; rr < 4; rr++) {
                int row = warp + 8 * rr;
                float* srow = Ss + row * SP;
                float v[16];
                float m = -1e30f;
                #pragma unroll
                for (int j = 0; j < 16; j++) {
                    v[j] = srow[lane + 32 * j] * 0.25f;
                    m = fmaxf(m, v[j]);
                }
                #pragma unroll
                for (int o = 16; o; o >>= 1)
                    m = fmaxf(m, __shfl_xor_sync(0xffffffffu, m, o));
                float s = 0.f;
                #pragma unroll
                for (int j = 0; j < 16; j++) { v[j] = __expf(v[j] - m); s += v[j]; }
                #pragma unroll
                for (int o = 16; o; o >>= 1)
                    s += __shfl_xor_sync(0xffffffffu, s, o);
                float inv = 1.f / s;
                #pragma unroll
                for (int j = 0; j < 16; j++) srow[lane + 32 * j] = v[j] * inv;
            }
        }
        __syncthreads();

        // ---------- phase 3: O_partial = P V over warp's 64-key slice ----------
        // lane owns queries {qg + 4i, i=0..7}, dims {2dg, 2dg+1}.
        // Per load instruction (fixed i): 4 distinct Ss rows spaced 1 apart,
        // banks offset by SP mod 32 = 12 -> conflict-free (8-way broadcast).
        {
            int qg = lane >> 3;           // 0..3
            int dg = lane & 7;            // 0..7
            float acc[8][2];
            #pragma unroll
            for (int i = 0; i < 8; i++) { acc[i][0] = 0.f; acc[i][1] = 0.f; }
            int kbase = warp * 64;
            #pragma unroll 4
            for (int t = 0; t < 64; t++) {
                int k = kbase + t;
                float2 v2 = *(const float2*)&Vs[k * VP + dg * 2];
                #pragma unroll
                for (int i = 0; i < 8; i++) {
                    float p = Ss[(qg + 4 * i) * SP + k];
                    acc[i][0] = fmaf(p, v2.x, acc[i][0]);
                    acc[i][1] = fmaf(p, v2.y, acc[i][1]);
                }
            }
            #pragma unroll
            for (int i = 0; i < 8; i++) {
                float2* dst = (float2*)&Op[(warp * 32 + qg + 4 * i) * OPP + dg * 2];
                *dst = make_float2(acc[i][0], acc[i][1]);
            }
        }
        __syncthreads();

        // ---------- reduce partials + LePE + store ----------
        #pragma unroll
        for (int rep = 0; rep < 2; rep++) {
            int idx = tid + 256 * rep;        // 0..511
            int q = idx >> 4;                 // 0..31
            int d = idx & 15;
            float o = 0.f;
            #pragma unroll
            for (int w = 0; w < 8; w++) o += Op[(w * 32 + q) * OPP + d];
            int n = qb + q;
            int h = n / WS, w2 = n % WS;
            float lep = bsm[d];
            #pragma unroll
            for (int ky = 0; ky < 3; ky++) {
                int hh = h + ky - 1;
                if (hh < 0 || hh >= HS) continue;
                #pragma unroll
                for (int kx = 0; kx < 3; kx++) {
                    int ww = w2 + kx - 1;
                    if (ww < 0 || ww >= WS) continue;
                    lep = fmaf(wsm[d * 9 + ky * 3 + kx],
                               Qt[d * QP + hh * WS + ww], lep);
                }
            }
            int l = tok_to_l(n, br, wn);
            g_att[((size_t)(b * L_DIM) + l) * C_DIM + cb + d] = o + lep;
        }
        __syncthreads();
    }
}

// ---------------------------------------------------------------------------
__global__ void __launch_bounds__(256) out_transpose_kernel(float* __restrict__ out) {
    __shared__ float sm[128][33];
    int b  = blockIdx.y;
    int l0 = blockIdx.x * 32;
    int tid = threadIdx.x;
    const float* yb = g_y + ((size_t)b * L_DIM + l0) * C_DIM;
    #pragma unroll
    for (int r = 0; r < 16; r++) {
        int i = r * 256 + tid;
        int lloc = i >> 7, c = i & 127;
        sm[c][lloc] = yb[(size_t)lloc * C_DIM + c];
    }
    __syncthreads();
    #pragma unroll
    for (int r = 0; r < 16; r++) {
        int c = r * 8 + (tid >> 5);
        int j = tid & 31;
        out[(size_t)b * C_DIM * L_DIM + (size_t)c * L_DIM + l0 + j] = sm[c][j];
    }
}

// ---------------------------------------------------------------------------
extern "C" void kernel_launch(void* const* d_in, const int* in_sizes, int n_in,
                              void* d_out, int out_size) {
    const float* x       = (const float*)d_in[0];
    const float* z       = (const float*)d_in[1];
    const float* ln1_g   = (const float*)d_in[2];
    const float* ln1_b   = (const float*)d_in[3];
    const float* ln2_g   = (const float*)d_in[4];
    const float* ln2_b   = (const float*)d_in[5];
    const float* Wz1     = (const float*)d_in[6];
    const float* Wz2     = (const float*)d_in[7];
    const float* Wqkv    = (const float*)d_in[8];
    const float* Wproj   = (const float*)d_in[9];
    const float* bproj   = (const float*)d_in[10];
    const float* lepe_w0 = (const float*)d_in[11];
    const float* lepe_b0 = (const float*)d_in[12];
    const float* lepe_w1 = (const float*)d_in[13];
    const float* lepe_b1 = (const float*)d_in[14];
    const float* W1      = (const float*)d_in[15];
    const float* b1      = (const float*)d_in[16];
    const float* W2      = (const float*)d_in[17];
    const float* b2      = (const float*)d_in[18];
    float* out = (float*)d_out;

    float* p_xf;  cudaGetSymbolAddress((void**)&p_xf,  g_xf);
    float* p_h1;  cudaGetSymbolAddress((void**)&p_h1,  g_h1);
    float* p_qkv; cudaGetSymbolAddress((void**)&p_qkv, g_qkv);
    float* p_att; cudaGetSymbolAddress((void**)&p_att, g_att);
    float* p_xf2; cudaGetSymbolAddress((void**)&p_xf2, g_xf2);
    float* p_h2;  cudaGetSymbolAddress((void**)&p_h2,  g_h2);
    float* p_mid; cudaGetSymbolAddress((void**)&p_mid, g_mid);
    float* p_y;   cudaGetSymbolAddress((void**)&p_y,   g_y);

    const int attn_smem = ATTN_SMEM_FLOATS * (int)sizeof(float);
    cudaFuncSetAttribute(attn_kernel, cudaFuncAttributeMaxDynamicSharedMemorySize, attn_smem);

    zproj_kernel<<<8, 256>>>(z, Wz1, Wz2);
    ln1_kernel<<<dim3(128, 8), 256>>>(x, ln1_g, ln1_b);
    gemm_kernel<<<dim3(QKV_N / BN, M_ROWS / BM), 256>>>(
        p_h1, Wqkv, nullptr, nullptr, p_qkv, M_ROWS, QKV_N, C_DIM, 0);
    attn_kernel<<<dim3(64, 4, 2), 256, attn_smem>>>(lepe_w0, lepe_b0, lepe_w1, lepe_b1);
    gemm_kernel<<<dim3(C_DIM / BN, M_ROWS / BM), 256>>>(
        p_att, Wproj, bproj, p_xf, p_xf2, M_ROWS, C_DIM, C_DIM, 0);
    ln2_kernel<<<M_ROWS / 8, 256>>>(ln2_g, ln2_b);
    gemm_kernel<<<dim3(HID / BN, M_ROWS / BM), 256>>>(
        p_h2, W1, b1, nullptr, p_mid, M_ROWS, HID, C_DIM, 1);
    gemm_kernel<<<dim3(C_DIM / BN, M_ROWS / BM), 256>>>(
        p_mid, W2, b2, p_xf2, p_y, M_ROWS, C_DIM, HID, 0);
    out_transpose_kernel<<<dim3(128, 8), 256>>>(out);
}

// round 5
// speedup vs baseline: 2.3660x; 1.3750x over previous
#include <cuda_runtime.h>
#include <cuda_bf16.h>
#include <cstdint>
#include <math.h>

// ---------------------------------------------------------------------------
// Problem constants
// ---------------------------------------------------------------------------
#define M_ROWS   32768
#define C_DIM    128
#define L_DIM    4096
#define B_DIM    8
#define HID      512
#define QKV_N    384
#define ZC       512

// ---------------------------------------------------------------------------
// Scratch buffers
// ---------------------------------------------------------------------------
__device__ __align__(16) float g_xf [M_ROWS * C_DIM];
__device__ __align__(16) float g_h1 [M_ROWS * C_DIM];
__device__ __align__(16) float g_qkv[M_ROWS * QKV_N];
__device__ __align__(16) float g_att[M_ROWS * C_DIM];
__device__ __align__(16) float g_xf2[M_ROWS * C_DIM];
__device__ __align__(16) float g_h2 [M_ROWS * C_DIM];
__device__ __align__(16) float g_mid[M_ROWS * HID];
__device__ __align__(16) float g_y  [M_ROWS * C_DIM];
__device__ __align__(16) float g_z1 [B_DIM * C_DIM];
__device__ __align__(16) float g_z2 [B_DIM * C_DIM];

// ---------------------------------------------------------------------------
// helpers
// ---------------------------------------------------------------------------
__device__ __forceinline__ uint32_t f2tf32(float x) {
    uint32_t u;
    asm("cvt.rna.tf32.f32 %0, %1;" : "=r"(u) : "f"(x));
    return u;
}
__device__ __forceinline__ float gelu_f(float v) {
    return 0.5f * v * (1.f + erff(v * 0.70710678118654752f));
}
__device__ __forceinline__ void mma16n8k8(float* d, const uint32_t* a,
                                          const uint32_t* b) {
    asm("mma.sync.aligned.m16n8k8.row.col.f32.tf32.tf32.f32 "
        "{%0,%1,%2,%3}, {%4,%5,%6,%7}, {%8,%9}, {%0,%1,%2,%3};"
        : "+f"(d[0]), "+f"(d[1]), "+f"(d[2]), "+f"(d[3])
        : "r"(a[0]), "r"(a[1]), "r"(a[2]), "r"(a[3]), "r"(b[0]), "r"(b[1]));
}

// ---------------------------------------------------------------------------
__global__ void zproj_kernel(const float* __restrict__ z,
                             const float* __restrict__ Wz1,
                             const float* __restrict__ Wz2) {
    int o = blockIdx.x * 256 + threadIdx.x;
    if (o >= 2048) return;
    int which = o >> 10;
    int b = (o >> 7) & 7;
    int c = o & 127;
    const float* W = (which ? Wz2 : Wz1) + c * ZC;
    const float* zb = z + b * ZC;
    float s = 0.f;
    #pragma unroll 8
    for (int k = 0; k < ZC; k++) s += zb[k] * W[k];
    (which ? g_z2 : g_z1)[b * C_DIM + c] = s;
}

// ---------------------------------------------------------------------------
__global__ void __launch_bounds__(256) ln1_kernel(const float* __restrict__ x,
                                                  const float* __restrict__ gamma,
                                                  const float* __restrict__ beta) {
    __shared__ float sm[128][33];
    int b  = blockIdx.y;
    int l0 = blockIdx.x * 32;
    int tid = threadIdx.x;
    const float* xb = x + (size_t)b * C_DIM * L_DIM;
    #pragma unroll
    for (int r = 0; r < 16; r++) {
        int c = r * 8 + (tid >> 5);
        int j = tid & 31;
        sm[c][j] = xb[(size_t)c * L_DIM + l0 + j];
    }
    __syncthreads();
    int warp = tid >> 5, lane = tid & 31;
    #pragma unroll
    for (int rr = 0; rr < 4; rr++) {
        int j = warp + rr * 8;
        float v[4];
        float s = 0.f, s2 = 0.f;
        #pragma unroll
        for (int u = 0; u < 4; u++) {
            v[u] = sm[lane + 32 * u][j];
            s += v[u]; s2 += v[u] * v[u];
        }
        #pragma unroll
        for (int o = 16; o; o >>= 1) {
            s  += __shfl_xor_sync(0xffffffffu, s,  o);
            s2 += __shfl_xor_sync(0xffffffffu, s2, o);
        }
        float mu   = s  * (1.f / 128.f);
        float var  = s2 * (1.f / 128.f) - mu * mu;
        float rstd = rsqrtf(var + 1e-5f);
        int l = l0 + j;
        size_t row = ((size_t)b * L_DIM + l) * C_DIM;
        #pragma unroll
        for (int u = 0; u < 4; u++) {
            int c = lane + 32 * u;
            g_xf[row + c] = v[u];
            g_h1[row + c] = (v[u] - mu) * rstd * gamma[c] + beta[c]
                          + g_z1[b * C_DIM + c];
        }
    }
}

// ---------------------------------------------------------------------------
__global__ void __launch_bounds__(256) ln2_kernel(const float* __restrict__ gamma,
                                                  const float* __restrict__ beta) {
    int row  = blockIdx.x * 8 + (threadIdx.x >> 5);
    int lane = threadIdx.x & 31;
    int b = row >> 12;
    const float* xr = g_xf2 + (size_t)row * C_DIM;
    float v[4]; float s = 0.f, s2 = 0.f;
    #pragma unroll
    for (int u = 0; u < 4; u++) {
        v[u] = xr[lane + 32 * u];
        s += v[u]; s2 += v[u] * v[u];
    }
    #pragma unroll
    for (int o = 16; o; o >>= 1) {
        s  += __shfl_xor_sync(0xffffffffu, s,  o);
        s2 += __shfl_xor_sync(0xffffffffu, s2, o);
    }
    float mu   = s  * (1.f / 128.f);
    float var  = s2 * (1.f / 128.f) - mu * mu;
    float rstd = rsqrtf(var + 1e-5f);
    float* hr = g_h2 + (size_t)row * C_DIM;
    #pragma unroll
    for (int u = 0; u < 4; u++) {
        int c = lane + 32 * u;
        hr[c] = (v[u] - mu) * rstd * gamma[c] + beta[c] + g_z2[b * C_DIM + c];
    }
}

// ---------------------------------------------------------------------------
// Tensor-core GEMM via mma.sync (tf32, m16n8k8):
//   C[m,n] = act( res[m,n] + bias[n] + sum_k A[m,k]*W[n,k] )
// CTA tile 128x128, BK=16, 8 warps in 2(m) x 4(n), warp tile 64x32.
// smem [k][m] / [k][n], stride 136 floats (136 mod 32 = 8 -> fragment loads
// hit banks 8t+g, all 32 distinct).  K % 16 == 0.
// ---------------------------------------------------------------------------
#define GBK 16
#define GST 136

__global__ void __launch_bounds__(256) gemm_mma_kernel(
        const float* __restrict__ A, const float* __restrict__ W,
        const float* __restrict__ bias, const float* __restrict__ res,
        float* __restrict__ C, int M, int N, int K, int act) {
    __shared__ uint32_t As[GBK * GST];
    __shared__ uint32_t Bs[GBK * GST];
    int tid  = threadIdx.x;
    int warp = tid >> 5, lane = tid & 31;
    int wm = warp >> 2;                 // 0..1
    int wn = warp & 3;                  // 0..3
    int t = lane & 3, g = lane >> 2;    // mma quad coords
    int m0 = blockIdx.y * 128, n0 = blockIdx.x * 128;

    float acc[4][4][4];
    #pragma unroll
    for (int i = 0; i < 4; i++)
        #pragma unroll
        for (int j = 0; j < 4; j++)
            #pragma unroll
            for (int r = 0; r < 4; r++) acc[i][j][r] = 0.f;

    int lrow0 = tid >> 2;               // 0..63   (r=0)
    int lkc   = (tid & 3) << 2;         // 0,4,8,12
    float4 pa[2], pb[2];

    // prefetch slab 0
    #pragma unroll
    for (int r = 0; r < 2; r++) {
        int row = lrow0 + (r << 6);
        pa[r] = *(const float4*)(A + (size_t)(m0 + row) * K + lkc);
        pb[r] = *(const float4*)(W + (size_t)(n0 + row) * K + lkc);
    }

    int slabs = K >> 4;
    for (int s = 0; s < slabs; s++) {
        // store current slab to smem (tf32-rounded)
        #pragma unroll
        for (int r = 0; r < 2; r++) {
            int row = lrow0 + (r << 6);
            As[(lkc + 0) * GST + row] = f2tf32(pa[r].x);
            As[(lkc + 1) * GST + row] = f2tf32(pa[r].y);
            As[(lkc + 2) * GST + row] = f2tf32(pa[r].z);
            As[(lkc + 3) * GST + row] = f2tf32(pa[r].w);
            Bs[(lkc + 0) * GST + row] = f2tf32(pb[r].x);
            Bs[(lkc + 1) * GST + row] = f2tf32(pb[r].y);
            Bs[(lkc + 2) * GST + row] = f2tf32(pb[r].z);
            Bs[(lkc + 3) * GST + row] = f2tf32(pb[r].w);
        }
        __syncthreads();
        // prefetch next slab while MMAs run
        if (s + 1 < slabs) {
            int k0 = (s + 1) << 4;
            #pragma unroll
            for (int r = 0; r < 2; r++) {
                int row = lrow0 + (r << 6);
                pa[r] = *(const float4*)(A + (size_t)(m0 + row) * K + k0 + lkc);
                pb[r] = *(const float4*)(W + (size_t)(n0 + row) * K + k0 + lkc);
            }
        }
        #pragma unroll
        for (int kk = 0; kk < GBK; kk += 8) {
            const uint32_t* ak = As + (kk + t) * GST + wm * 64 + g;
            uint32_t af[4][4];
            #pragma unroll
            for (int f = 0; f < 4; f++) {
                const uint32_t* p = ak + f * 16;
                af[f][0] = p[0];
                af[f][1] = p[8];
                af[f][2] = p[4 * GST];
                af[f][3] = p[4 * GST + 8];
            }
            const uint32_t* bk = Bs + (kk + t) * GST + wn * 32 + g;
            uint32_t bf[4][2];
            #pragma unroll
            for (int f = 0; f < 4; f++) {
                bf[f][0] = bk[f * 8];
                bf[f][1] = bk[f * 8 + 4 * GST];
            }
            #pragma unroll
            for (int i = 0; i < 4; i++)
                #pragma unroll
                for (int j = 0; j < 4; j++)
                    mma16n8k8(acc[i][j], af[i], bf[j]);
        }
        __syncthreads();
    }

    // epilogue: acc[i][j] regs {0,1}->row g, {2,3}->row g+8; cols 2t,2t+1
    #pragma unroll
    for (int i = 0; i < 4; i++) {
        int mr = m0 + wm * 64 + i * 16 + g;
        #pragma unroll
        for (int half = 0; half < 2; half++) {
            int m = mr + 8 * half;
            size_t ro = (size_t)m * N;
            #pragma unroll
            for (int j = 0; j < 4; j++) {
                int n = n0 + wn * 32 + j * 8 + 2 * t;
                float vx = acc[i][j][2 * half];
                float vy = acc[i][j][2 * half + 1];
                if (bias) { vx += bias[n]; vy += bias[n + 1]; }
                if (res) {
                    float2 rv = *(const float2*)(res + ro + n);
                    vx += rv.x; vy += rv.y;
                }
                if (act) { vx = gelu_f(vx); vy = gelu_f(vy); }
                float2 ov = make_float2(vx, vy);
                *(float2*)(C + ro + n) = ov;
            }
        }
    }
}

// ---------------------------------------------------------------------------
// Register-tiled windowed attention + LePE (unchanged from passing R3).
// ---------------------------------------------------------------------------
#define QP 520
#define VP 20
#define SP 524
#define OPP 18
#define OFF_QT 0
#define OFF_KT (16*QP)
#define OFF_V  (2*16*QP)
#define OFF_SS (OFF_V + 512*VP)
#define OFF_OP (OFF_SS + 32*SP)
#define OFF_W  (OFF_OP + 8*32*OPP)
#define OFF_B  (OFF_W + 144)
#define ATTN_SMEM_FLOATS (OFF_B + 16)

__device__ __forceinline__ int tok_to_l(int n, int br, int wn) {
    if (br == 0) { int h = n >> 3, w = n & 7; return h * 64 + wn * 8 + w; }
    return wn * 512 + n;
}

__global__ void __launch_bounds__(256) attn_kernel(
        const float* __restrict__ lepe_w0, const float* __restrict__ lepe_b0,
        const float* __restrict__ lepe_w1, const float* __restrict__ lepe_b1) {
    extern __shared__ float smf[];
    float* Qt = smf + OFF_QT;
    float* Kt = smf + OFF_KT;
    float* Vs = smf + OFF_V;
    float* Ss = smf + OFF_SS;
    float* Op = smf + OFF_OP;
    float* wsm = smf + OFF_W;
    float* bsm = smf + OFF_B;

    int wglob = blockIdx.x;
    int hd    = blockIdx.y;
    int br    = blockIdx.z;
    int b  = wglob >> 3;
    int wn = wglob & 7;
    int cb = br * 64 + hd * 16;
    int tid  = threadIdx.x;
    int warp = tid >> 5, lane = tid & 31;

    for (int t = tid; t < 512; t += 256) {
        int l = tok_to_l(t, br, wn);
        const float* base = g_qkv + ((size_t)(b * L_DIM + l)) * QKV_N + cb;
        float4 q0 = ((const float4*)base)[0], q1 = ((const float4*)base)[1];
        float4 q2 = ((const float4*)base)[2], q3 = ((const float4*)base)[3];
        Qt[ 0*QP+t]=q0.x; Qt[ 1*QP+t]=q0.y; Qt[ 2*QP+t]=q0.z; Qt[ 3*QP+t]=q0.w;
        Qt[ 4*QP+t]=q1.x; Qt[ 5*QP+t]=q1.y; Qt[ 6*QP+t]=q1.z; Qt[ 7*QP+t]=q1.w;
        Qt[ 8*QP+t]=q2.x; Qt[ 9*QP+t]=q2.y; Qt[10*QP+t]=q2.z; Qt[11*QP+t]=q2.w;
        Qt[12*QP+t]=q3.x; Qt[13*QP+t]=q3.y; Qt[14*QP+t]=q3.z; Qt[15*QP+t]=q3.w;
        const float4* kp = (const float4*)(base + 128);
        float4 k0 = kp[0], k1 = kp[1], k2 = kp[2], k3 = kp[3];
        Kt[ 0*QP+t]=k0.x; Kt[ 1*QP+t]=k0.y; Kt[ 2*QP+t]=k0.z; Kt[ 3*QP+t]=k0.w;
        Kt[ 4*QP+t]=k1.x; Kt[ 5*QP+t]=k1.y; Kt[ 6*QP+t]=k1.z; Kt[ 7*QP+t]=k1.w;
        Kt[ 8*QP+t]=k2.x; Kt[ 9*QP+t]=k2.y; Kt[10*QP+t]=k2.z; Kt[11*QP+t]=k2.w;
        Kt[12*QP+t]=k3.x; Kt[13*QP+t]=k3.y; Kt[14*QP+t]=k3.z; Kt[15*QP+t]=k3.w;
        const float4* vp = (const float4*)(base + 256);
        float4* vdst = (float4*)&Vs[t * VP];
        vdst[0] = vp[0]; vdst[1] = vp[1]; vdst[2] = vp[2]; vdst[3] = vp[3];
    }
    const float* lw = br ? lepe_w1 : lepe_w0;
    const float* lb = br ? lepe_b1 : lepe_b0;
    if (tid < 144) wsm[tid] = lw[hd * 16 * 9 + tid];
    if (tid < 16)  bsm[tid] = lb[hd * 16 + tid];
    __syncthreads();

    const int HS = br ? 8 : 64;
    const int WS = br ? 64 : 8;

    #pragma unroll 1
    for (int pass = 0; pass < 16; pass++) {
        int qb = pass * 32;
        {
            int qg = lane >> 2;
            int kg = lane & 3;
            int kbase = warp * 64;
            const float* qa = Qt + qb + qg * 4;
            const float* ka = Kt + kbase + kg * 4;
            float acc[4][16];
            #pragma unroll
            for (int i = 0; i < 4; i++)
                #pragma unroll
                for (int j = 0; j < 16; j++) acc[i][j] = 0.f;
            #pragma unroll 4
            for (int d = 0; d < 16; d++) {
                float a[4], bx[16];
                *(float4*)a = *(const float4*)(qa + d * QP);
                *(float4*)&bx[ 0] = *(const float4*)(ka + d * QP);
                *(float4*)&bx[ 4] = *(const float4*)(ka + d * QP + 16);
                *(float4*)&bx[ 8] = *(const float4*)(ka + d * QP + 32);
                *(float4*)&bx[12] = *(const float4*)(ka + d * QP + 48);
                #pragma unroll
                for (int i = 0; i < 4; i++)
                    #pragma unroll
                    for (int j = 0; j < 16; j++)
                        acc[i][j] = fmaf(a[i], bx[j], acc[i][j]);
            }
            #pragma unroll
            for (int i = 0; i < 4; i++) {
                float* srow = Ss + (qg * 4 + i) * SP + kbase + kg * 4;
                #pragma unroll
                for (int j = 0; j < 4; j++)
                    *(float4*)(srow + 16 * j) = *(float4*)&acc[i][4 * j];
            }
        }
        __syncthreads();
        {
            #pragma unroll
            for (int rr = 0; rr < 4; rr++) {
                int row = warp + 8 * rr;
                float* srow = Ss + row * SP;
                float v[16];
                float m = -1e30f;
                #pragma unroll
                for (int j = 0; j < 16; j++) {
                    v[j] = srow[lane + 32 * j] * 0.25f;
                    m = fmaxf(m, v[j]);
                }
                #pragma unroll
                for (int o = 16; o; o >>= 1)
                    m = fmaxf(m, __shfl_xor_sync(0xffffffffu, m, o));
                float s = 0.f;
                #pragma unroll
                for (int j = 0; j < 16; j++) { v[j] = __expf(v[j] - m); s += v[j]; }
                #pragma unroll
                for (int o = 16; o; o >>= 1)
                    s += __shfl_xor_sync(0xffffffffu, s, o);
                float inv = 1.f / s;
                #pragma unroll
                for (int j = 0; j < 16; j++) srow[lane + 32 * j] = v[j] * inv;
            }
        }
        __syncthreads();
        {
            int qg = lane >> 3;
            int dg = lane & 7;
            float acc[8][2];
            #pragma unroll
            for (int i = 0; i < 8; i++) { acc[i][0] = 0.f; acc[i][1] = 0.f; }
            int kbase = warp * 64;
            #pragma unroll 4
            for (int t = 0; t < 64; t++) {
                int k = kbase + t;
                float2 v2 = *(const float2*)&Vs[k * VP + dg * 2];
                #pragma unroll
                for (int i = 0; i < 8; i++) {
                    float p = Ss[(qg + 4 * i) * SP + k];
                    acc[i][0] = fmaf(p, v2.x, acc[i][0]);
                    acc[i][1] = fmaf(p, v2.y, acc[i][1]);
                }
            }
            #pragma unroll
            for (int i = 0; i < 8; i++) {
                float2* dst = (float2*)&Op[(warp * 32 + qg + 4 * i) * OPP + dg * 2];
                *dst = make_float2(acc[i][0], acc[i][1]);
            }
        }
        __syncthreads();

        #pragma unroll
        for (int rep = 0; rep < 2; rep++) {
            int idx = tid + 256 * rep;
            int q = idx >> 4;
            int d = idx & 15;
            float o = 0.f;
            #pragma unroll
            for (int w = 0; w < 8; w++) o += Op[(w * 32 + q) * OPP + d];
            int n = qb + q;
            int h = n / WS, w2 = n % WS;
            float lep = bsm[d];
            #pragma unroll
            for (int ky = 0; ky < 3; ky++) {
                int hh = h + ky - 1;
                if (hh < 0 || hh >= HS) continue;
                #pragma unroll
                for (int kx = 0; kx < 3; kx++) {
                    int ww = w2 + kx - 1;
                    if (ww < 0 || ww >= WS) continue;
                    lep = fmaf(wsm[d * 9 + ky * 3 + kx],
                               Qt[d * QP + hh * WS + ww], lep);
                }
            }
            int l = tok_to_l(n, br, wn);
            g_att[((size_t)(b * L_DIM) + l) * C_DIM + cb + d] = o + lep;
        }
        __syncthreads();
    }
}

// ---------------------------------------------------------------------------
__global__ void __launch_bounds__(256) out_transpose_kernel(float* __restrict__ out) {
    __shared__ float sm[128][33];
    int b  = blockIdx.y;
    int l0 = blockIdx.x * 32;
    int tid = threadIdx.x;
    const float* yb = g_y + ((size_t)b * L_DIM + l0) * C_DIM;
    #pragma unroll
    for (int r = 0; r < 16; r++) {
        int i = r * 256 + tid;
        int lloc = i >> 7, c = i & 127;
        sm[c][lloc] = yb[(size_t)lloc * C_DIM + c];
    }
    __syncthreads();
    #pragma unroll
    for (int r = 0; r < 16; r++) {
        int c = r * 8 + (tid >> 5);
        int j = tid & 31;
        out[(size_t)b * C_DIM * L_DIM + (size_t)c * L_DIM + l0 + j] = sm[c][j];
    }
}

// ---------------------------------------------------------------------------
extern "C" void kernel_launch(void* const* d_in, const int* in_sizes, int n_in,
                              void* d_out, int out_size) {
    const float* x       = (const float*)d_in[0];
    const float* z       = (const float*)d_in[1];
    const float* ln1_g   = (const float*)d_in[2];
    const float* ln1_b   = (const float*)d_in[3];
    const float* ln2_g   = (const float*)d_in[4];
    const float* ln2_b   = (const float*)d_in[5];
    const float* Wz1     = (const float*)d_in[6];
    const float* Wz2     = (const float*)d_in[7];
    const float* Wqkv    = (const float*)d_in[8];
    const float* Wproj   = (const float*)d_in[9];
    const float* bproj   = (const float*)d_in[10];
    const float* lepe_w0 = (const float*)d_in[11];
    const float* lepe_b0 = (const float*)d_in[12];
    const float* lepe_w1 = (const float*)d_in[13];
    const float* lepe_b1 = (const float*)d_in[14];
    const float* W1      = (const float*)d_in[15];
    const float* b1      = (const float*)d_in[16];
    const float* W2      = (const float*)d_in[17];
    const float* b2      = (const float*)d_in[18];
    float* out = (float*)d_out;

    float* p_xf;  cudaGetSymbolAddress((void**)&p_xf,  g_xf);
    float* p_h1;  cudaGetSymbolAddress((void**)&p_h1,  g_h1);
    float* p_qkv; cudaGetSymbolAddress((void**)&p_qkv, g_qkv);
    float* p_att; cudaGetSymbolAddress((void**)&p_att, g_att);
    float* p_xf2; cudaGetSymbolAddress((void**)&p_xf2, g_xf2);
    float* p_h2;  cudaGetSymbolAddress((void**)&p_h2,  g_h2);
    float* p_mid; cudaGetSymbolAddress((void**)&p_mid, g_mid);
    float* p_y;   cudaGetSymbolAddress((void**)&p_y,   g_y);

    const int attn_smem = ATTN_SMEM_FLOATS * (int)sizeof(float);
    cudaFuncSetAttribute(attn_kernel, cudaFuncAttributeMaxDynamicSharedMemorySize, attn_smem);

    zproj_kernel<<<8, 256>>>(z, Wz1, Wz2);
    ln1_kernel<<<dim3(128, 8), 256>>>(x, ln1_g, ln1_b);
    gemm_mma_kernel<<<dim3(QKV_N / 128, M_ROWS / 128), 256>>>(
        p_h1, Wqkv, nullptr, nullptr, p_qkv, M_ROWS, QKV_N, C_DIM, 0);
    attn_kernel<<<dim3(64, 4, 2), 256, attn_smem>>>(lepe_w0, lepe_b0, lepe_w1, lepe_b1);
    gemm_mma_kernel<<<dim3(C_DIM / 128, M_ROWS / 128), 256>>>(
        p_att, Wproj, bproj, p_xf, p_xf2, M_ROWS, C_DIM, C_DIM, 0);
    ln2_kernel<<<M_ROWS / 8, 256>>>(ln2_g, ln2_b);
    gemm_mma_kernel<<<dim3(HID / 128, M_ROWS / 128), 256>>>(
        p_h2, W1, b1, nullptr, p_mid, M_ROWS, HID, C_DIM, 1);
    gemm_mma_kernel<<<dim3(C_DIM / 128, M_ROWS / 128), 256>>>(
        p_mid, W2, b2, p_xf2, p_y, M_ROWS, C_DIM, HID, 0);
    out_transpose_kernel<<<dim3(128, 8), 256>>>(out);
}

// round 6
// speedup vs baseline: 3.1041x; 1.3119x over previous
#include <cuda_runtime.h>
#include <cuda_bf16.h>
#include <cstdint>
#include <math.h>

// ---------------------------------------------------------------------------
// Problem constants
// ---------------------------------------------------------------------------
#define M_ROWS   32768
#define C_DIM    128
#define L_DIM    4096
#define B_DIM    8
#define HID      512
#define QKV_N    384
#define ZC       512

// ---------------------------------------------------------------------------
// Scratch buffers
// ---------------------------------------------------------------------------
__device__ __align__(16) float g_xf [M_ROWS * C_DIM];
__device__ __align__(16) float g_h1 [M_ROWS * C_DIM];
__device__ __align__(16) float g_qkv[M_ROWS * QKV_N];
__device__ __align__(16) float g_att[M_ROWS * C_DIM];
__device__ __align__(16) float g_xf2[M_ROWS * C_DIM];
__device__ __align__(16) float g_h2 [M_ROWS * C_DIM];
__device__ __align__(16) float g_mid[M_ROWS * HID];
__device__ __align__(16) float g_y  [M_ROWS * C_DIM];
__device__ __align__(16) float g_z1 [B_DIM * C_DIM];
__device__ __align__(16) float g_z2 [B_DIM * C_DIM];

// ---------------------------------------------------------------------------
// helpers
// ---------------------------------------------------------------------------
__device__ __forceinline__ uint32_t f2tf32(float x) {
    uint32_t u;
    asm("cvt.rna.tf32.f32 %0, %1;" : "=r"(u) : "f"(x));
    return u;
}
__device__ __forceinline__ float gelu_f(float v) {
    return 0.5f * v * (1.f + erff(v * 0.70710678118654752f));
}
__device__ __forceinline__ void mma16n8k8(float* d, const uint32_t* a,
                                          const uint32_t* b) {
    asm("mma.sync.aligned.m16n8k8.row.col.f32.tf32.tf32.f32 "
        "{%0,%1,%2,%3}, {%4,%5,%6,%7}, {%8,%9}, {%0,%1,%2,%3};"
        : "+f"(d[0]), "+f"(d[1]), "+f"(d[2]), "+f"(d[3])
        : "r"(a[0]), "r"(a[1]), "r"(a[2]), "r"(a[3]), "r"(b[0]), "r"(b[1]));
}

// ---------------------------------------------------------------------------
__global__ void zproj_kernel(const float* __restrict__ z,
                             const float* __restrict__ Wz1,
                             const float* __restrict__ Wz2) {
    int o = blockIdx.x * 256 + threadIdx.x;
    if (o >= 2048) return;
    int which = o >> 10;
    int b = (o >> 7) & 7;
    int c = o & 127;
    const float* W = (which ? Wz2 : Wz1) + c * ZC;
    const float* zb = z + b * ZC;
    float s = 0.f;
    #pragma unroll 8
    for (int k = 0; k < ZC; k++) s += zb[k] * W[k];
    (which ? g_z2 : g_z1)[b * C_DIM + c] = s;
}

// ---------------------------------------------------------------------------
__global__ void __launch_bounds__(256) ln1_kernel(const float* __restrict__ x,
                                                  const float* __restrict__ gamma,
                                                  const float* __restrict__ beta) {
    __shared__ float sm[128][33];
    int b  = blockIdx.y;
    int l0 = blockIdx.x * 32;
    int tid = threadIdx.x;
    const float* xb = x + (size_t)b * C_DIM * L_DIM;
    #pragma unroll
    for (int r = 0; r < 16; r++) {
        int c = r * 8 + (tid >> 5);
        int j = tid & 31;
        sm[c][j] = xb[(size_t)c * L_DIM + l0 + j];
    }
    __syncthreads();
    int warp = tid >> 5, lane = tid & 31;
    #pragma unroll
    for (int rr = 0; rr < 4; rr++) {
        int j = warp + rr * 8;
        float v[4];
        float s = 0.f, s2 = 0.f;
        #pragma unroll
        for (int u = 0; u < 4; u++) {
            v[u] = sm[lane + 32 * u][j];
            s += v[u]; s2 += v[u] * v[u];
        }
        #pragma unroll
        for (int o = 16; o; o >>= 1) {
            s  += __shfl_xor_sync(0xffffffffu, s,  o);
            s2 += __shfl_xor_sync(0xffffffffu, s2, o);
        }
        float mu   = s  * (1.f / 128.f);
        float var  = s2 * (1.f / 128.f) - mu * mu;
        float rstd = rsqrtf(var + 1e-5f);
        int l = l0 + j;
        size_t row = ((size_t)b * L_DIM + l) * C_DIM;
        #pragma unroll
        for (int u = 0; u < 4; u++) {
            int c = lane + 32 * u;
            g_xf[row + c] = v[u];
            g_h1[row + c] = (v[u] - mu) * rstd * gamma[c] + beta[c]
                          + g_z1[b * C_DIM + c];
        }
    }
}

// ---------------------------------------------------------------------------
__global__ void __launch_bounds__(256) ln2_kernel(const float* __restrict__ gamma,
                                                  const float* __restrict__ beta) {
    int row  = blockIdx.x * 8 + (threadIdx.x >> 5);
    int lane = threadIdx.x & 31;
    int b = row >> 12;
    const float* xr = g_xf2 + (size_t)row * C_DIM;
    float v[4]; float s = 0.f, s2 = 0.f;
    #pragma unroll
    for (int u = 0; u < 4; u++) {
        v[u] = xr[lane + 32 * u];
        s += v[u]; s2 += v[u] * v[u];
    }
    #pragma unroll
    for (int o = 16; o; o >>= 1) {
        s  += __shfl_xor_sync(0xffffffffu, s,  o);
        s2 += __shfl_xor_sync(0xffffffffu, s2, o);
    }
    float mu   = s  * (1.f / 128.f);
    float var  = s2 * (1.f / 128.f) - mu * mu;
    float rstd = rsqrtf(var + 1e-5f);
    float* hr = g_h2 + (size_t)row * C_DIM;
    #pragma unroll
    for (int u = 0; u < 4; u++) {
        int c = lane + 32 * u;
        hr[c] = (v[u] - mu) * rstd * gamma[c] + beta[c] + g_z2[b * C_DIM + c];
    }
}

// ---------------------------------------------------------------------------
// Tensor-core GEMM via mma.sync (tf32) -- unchanged from R5 (passing).
// ---------------------------------------------------------------------------
#define GBK 16
#define GST 136

__global__ void __launch_bounds__(256) gemm_mma_kernel(
        const float* __restrict__ A, const float* __restrict__ W,
        const float* __restrict__ bias, const float* __restrict__ res,
        float* __restrict__ C, int M, int N, int K, int act) {
    __shared__ uint32_t As[GBK * GST];
    __shared__ uint32_t Bs[GBK * GST];
    int tid  = threadIdx.x;
    int warp = tid >> 5, lane = tid & 31;
    int wm = warp >> 2;
    int wn = warp & 3;
    int t = lane & 3, g = lane >> 2;
    int m0 = blockIdx.y * 128, n0 = blockIdx.x * 128;

    float acc[4][4][4];
    #pragma unroll
    for (int i = 0; i < 4; i++)
        #pragma unroll
        for (int j = 0; j < 4; j++)
            #pragma unroll
            for (int r = 0; r < 4; r++) acc[i][j][r] = 0.f;

    int lrow0 = tid >> 2;
    int lkc   = (tid & 3) << 2;
    float4 pa[2], pb[2];

    #pragma unroll
    for (int r = 0; r < 2; r++) {
        int row = lrow0 + (r << 6);
        pa[r] = *(const float4*)(A + (size_t)(m0 + row) * K + lkc);
        pb[r] = *(const float4*)(W + (size_t)(n0 + row) * K + lkc);
    }

    int slabs = K >> 4;
    for (int s = 0; s < slabs; s++) {
        #pragma unroll
        for (int r = 0; r < 2; r++) {
            int row = lrow0 + (r << 6);
            As[(lkc + 0) * GST + row] = f2tf32(pa[r].x);
            As[(lkc + 1) * GST + row] = f2tf32(pa[r].y);
            As[(lkc + 2) * GST + row] = f2tf32(pa[r].z);
            As[(lkc + 3) * GST + row] = f2tf32(pa[r].w);
            Bs[(lkc + 0) * GST + row] = f2tf32(pb[r].x);
            Bs[(lkc + 1) * GST + row] = f2tf32(pb[r].y);
            Bs[(lkc + 2) * GST + row] = f2tf32(pb[r].z);
            Bs[(lkc + 3) * GST + row] = f2tf32(pb[r].w);
        }
        __syncthreads();
        if (s + 1 < slabs) {
            int k0 = (s + 1) << 4;
            #pragma unroll
            for (int r = 0; r < 2; r++) {
                int row = lrow0 + (r << 6);
                pa[r] = *(const float4*)(A + (size_t)(m0 + row) * K + k0 + lkc);
                pb[r] = *(const float4*)(W + (size_t)(n0 + row) * K + k0 + lkc);
            }
        }
        #pragma unroll
        for (int kk = 0; kk < GBK; kk += 8) {
            const uint32_t* ak = As + (kk + t) * GST + wm * 64 + g;
            uint32_t af[4][4];
            #pragma unroll
            for (int f = 0; f < 4; f++) {
                const uint32_t* p = ak + f * 16;
                af[f][0] = p[0];
                af[f][1] = p[8];
                af[f][2] = p[4 * GST];
                af[f][3] = p[4 * GST + 8];
            }
            const uint32_t* bk = Bs + (kk + t) * GST + wn * 32 + g;
            uint32_t bf[4][2];
            #pragma unroll
            for (int f = 0; f < 4; f++) {
                bf[f][0] = bk[f * 8];
                bf[f][1] = bk[f * 8 + 4 * GST];
            }
            #pragma unroll
            for (int i = 0; i < 4; i++)
                #pragma unroll
                for (int j = 0; j < 4; j++)
                    mma16n8k8(acc[i][j], af[i], bf[j]);
        }
        __syncthreads();
    }

    #pragma unroll
    for (int i = 0; i < 4; i++) {
        int mr = m0 + wm * 64 + i * 16 + g;
        #pragma unroll
        for (int half = 0; half < 2; half++) {
            int m = mr + 8 * half;
            size_t ro = (size_t)m * N;
            #pragma unroll
            for (int j = 0; j < 4; j++) {
                int n = n0 + wn * 32 + j * 8 + 2 * t;
                float vx = acc[i][j][2 * half];
                float vy = acc[i][j][2 * half + 1];
                if (bias) { vx += bias[n]; vy += bias[n + 1]; }
                if (res) {
                    float2 rv = *(const float2*)(res + ro + n);
                    vx += rv.x; vy += rv.y;
                }
                if (act) { vx = gelu_f(vx); vy = gelu_f(vy); }
                float2 ov = make_float2(vx, vy);
                *(float2*)(C + ro + n) = ov;
            }
        }
    }
}

// ---------------------------------------------------------------------------
// Windowed attention + LePE, now with mma.sync tf32 for QK^T and PV.
// smem: Qt[16][520], Kt[16][520] (tf32 bits, [k][m]/[k][n] layouts)
//       Vs[512][24]  (tf32 bits, [k][n] layout for PV)
//       Ss[32][524]  (fp32 scores/probs, [q][k])
//       Op[8][32][18] per-warp PV partials
// 16 passes of 32 queries.
// ---------------------------------------------------------------------------
#define QP 520
#define VP 24
#define SP 524
#define OPP 18
#define OFF_QT 0
#define OFF_KT (16*QP)
#define OFF_V  (2*16*QP)
#define OFF_SS (OFF_V + 512*VP)
#define OFF_OP (OFF_SS + 32*SP)
#define OFF_W  (OFF_OP + 8*32*OPP)
#define OFF_B  (OFF_W + 144)
#define ATTN_SMEM_FLOATS (OFF_B + 16)

__device__ __forceinline__ int tok_to_l(int n, int br, int wn) {
    if (br == 0) { int h = n >> 3, w = n & 7; return h * 64 + wn * 8 + w; }
    return wn * 512 + n;
}

__global__ void __launch_bounds__(256) attn_kernel(
        const float* __restrict__ lepe_w0, const float* __restrict__ lepe_b0,
        const float* __restrict__ lepe_w1, const float* __restrict__ lepe_b1) {
    extern __shared__ float smf[];
    float*    Qt  = smf + OFF_QT;
    float*    Kt  = smf + OFF_KT;
    uint32_t* Qu  = (uint32_t*)Qt;
    uint32_t* Ku  = (uint32_t*)Kt;
    uint32_t* Vu  = (uint32_t*)(smf + OFF_V);
    float*    Ss  = smf + OFF_SS;
    float*    Op  = smf + OFF_OP;
    float*    wsm = smf + OFF_W;
    float*    bsm = smf + OFF_B;

    int wglob = blockIdx.x;
    int hd    = blockIdx.y;
    int br    = blockIdx.z;
    int b  = wglob >> 3;
    int wn = wglob & 7;
    int cb = br * 64 + hd * 16;
    int tid  = threadIdx.x;
    int warp = tid >> 5, lane = tid & 31;
    int g = lane >> 2, t = lane & 3;           // mma quad coords

    // ---- load Q,K transposed + V row-major, all tf32-rounded ----
    for (int tk = tid; tk < 512; tk += 256) {
        int l = tok_to_l(tk, br, wn);
        const float* base = g_qkv + ((size_t)(b * L_DIM + l)) * QKV_N + cb;
        #pragma unroll
        for (int d4 = 0; d4 < 4; d4++) {
            float4 q4 = ((const float4*)base)[d4];
            Qu[(d4*4+0)*QP + tk] = f2tf32(q4.x);
            Qu[(d4*4+1)*QP + tk] = f2tf32(q4.y);
            Qu[(d4*4+2)*QP + tk] = f2tf32(q4.z);
            Qu[(d4*4+3)*QP + tk] = f2tf32(q4.w);
            float4 k4 = ((const float4*)(base + 128))[d4];
            Ku[(d4*4+0)*QP + tk] = f2tf32(k4.x);
            Ku[(d4*4+1)*QP + tk] = f2tf32(k4.y);
            Ku[(d4*4+2)*QP + tk] = f2tf32(k4.z);
            Ku[(d4*4+3)*QP + tk] = f2tf32(k4.w);
            float4 v4 = ((const float4*)(base + 256))[d4];
            uint4 vt = { f2tf32(v4.x), f2tf32(v4.y), f2tf32(v4.z), f2tf32(v4.w) };
            *(uint4*)&Vu[tk * VP + d4 * 4] = vt;
        }
    }
    const float* lw = br ? lepe_w1 : lepe_w0;
    const float* lb = br ? lepe_b1 : lepe_b0;
    if (tid < 144) wsm[tid] = lw[hd * 16 * 9 + tid];
    if (tid < 16)  bsm[tid] = lb[hd * 16 + tid];
    __syncthreads();

    const int HS = br ? 8 : 64;
    const int WS = br ? 64 : 8;
    const int kw = warp * 64;                  // this warp's key slice

    #pragma unroll 1
    for (int pass = 0; pass < 16; pass++) {
        int qb = pass * 32;

        // ---------- phase 1: S = Q K^T via mma (warp: 32q x 64k) ----------
        {
            // A fragments (Q): 2 k-steps x 2 m-tiles
            uint32_t af[2][2][4];
            #pragma unroll
            for (int ks = 0; ks < 2; ks++)
                #pragma unroll
                for (int i = 0; i < 2; i++) {
                    const uint32_t* p = Qu + (ks*8 + t)*QP + qb + i*16 + g;
                    af[ks][i][0] = p[0];
                    af[ks][i][1] = p[8];
                    af[ks][i][2] = p[4*QP];
                    af[ks][i][3] = p[4*QP + 8];
                }
            // B fragments (K): 2 k-steps x 8 n-tiles
            uint32_t bf[2][8][2];
            #pragma unroll
            for (int ks = 0; ks < 2; ks++)
                #pragma unroll
                for (int j = 0; j < 8; j++) {
                    const uint32_t* p = Ku + (ks*8 + t)*QP + kw + j*8 + g;
                    bf[ks][j][0] = p[0];
                    bf[ks][j][1] = p[4*QP];
                }
            float acc[2][8][4];
            #pragma unroll
            for (int i = 0; i < 2; i++)
                #pragma unroll
                for (int j = 0; j < 8; j++) {
                    acc[i][j][0] = 0.f; acc[i][j][1] = 0.f;
                    acc[i][j][2] = 0.f; acc[i][j][3] = 0.f;
                }
            #pragma unroll
            for (int i = 0; i < 2; i++)
                #pragma unroll
                for (int j = 0; j < 8; j++) {
                    mma16n8k8(acc[i][j], af[0][i], bf[0][j]);
                    mma16n8k8(acc[i][j], af[1][i], bf[1][j]);
                }
            #pragma unroll
            for (int i = 0; i < 2; i++)
                #pragma unroll
                for (int j = 0; j < 8; j++) {
                    int col = kw + j*8 + 2*t;
                    *(float2*)&Ss[(i*16 + g    ) * SP + col] =
                        make_float2(acc[i][j][0], acc[i][j][1]);
                    *(float2*)&Ss[(i*16 + g + 8) * SP + col] =
                        make_float2(acc[i][j][2], acc[i][j][3]);
                }
        }
        __syncthreads();

        // ---------- phase 2: softmax rows (scale 0.25) ----------
        {
            #pragma unroll
            for (int rr = 0; rr < 4; rr++) {
                int row = warp + 8 * rr;
                float* srow = Ss + row * SP;
                float v[16];
                float m = -1e30f;
                #pragma unroll
                for (int j = 0; j < 16; j++) {
                    v[j] = srow[lane + 32 * j] * 0.25f;
                    m = fmaxf(m, v[j]);
                }
                #pragma unroll
                for (int o = 16; o; o >>= 1)
                    m = fmaxf(m, __shfl_xor_sync(0xffffffffu, m, o));
                float s = 0.f;
                #pragma unroll
                for (int j = 0; j < 16; j++) { v[j] = __expf(v[j] - m); s += v[j]; }
                #pragma unroll
                for (int o = 16; o; o >>= 1)
                    s += __shfl_xor_sync(0xffffffffu, s, o);
                float inv = 1.f / s;
                #pragma unroll
                for (int j = 0; j < 16; j++) srow[lane + 32 * j] = v[j] * inv;
            }
        }
        __syncthreads();

        // ---------- phase 3: O_partial = P V via mma (warp's 64-key slice) ----
        {
            float oacc[2][2][4];
            #pragma unroll
            for (int i = 0; i < 2; i++)
                #pragma unroll
                for (int j = 0; j < 2; j++) {
                    oacc[i][j][0] = 0.f; oacc[i][j][1] = 0.f;
                    oacc[i][j][2] = 0.f; oacc[i][j][3] = 0.f;
                }
            #pragma unroll
            for (int ks = 0; ks < 8; ks++) {
                int k0 = kw + ks * 8;
                // A frags: P from Ss[q][k] (transposed access, cvt to tf32)
                uint32_t paf[2][4];
                #pragma unroll
                for (int i = 0; i < 2; i++) {
                    const float* p = Ss + (i*16 + g) * SP + k0 + t;
                    paf[i][0] = f2tf32(p[0]);
                    paf[i][1] = f2tf32(p[8*SP]);
                    paf[i][2] = f2tf32(p[4]);
                    paf[i][3] = f2tf32(p[8*SP + 4]);
                }
                // B frags: V from Vs[k][n] stride 24
                uint32_t vbf[2][2];
                #pragma unroll
                for (int j = 0; j < 2; j++) {
                    const uint32_t* p = Vu + (k0 + t) * VP + j*8 + g;
                    vbf[j][0] = p[0];
                    vbf[j][1] = p[4*VP];
                }
                #pragma unroll
                for (int i = 0; i < 2; i++)
                    #pragma unroll
                    for (int j = 0; j < 2; j++)
                        mma16n8k8(oacc[i][j], paf[i], vbf[j]);
            }
            #pragma unroll
            for (int i = 0; i < 2; i++)
                #pragma unroll
                for (int j = 0; j < 2; j++) {
                    int col = j*8 + 2*t;
                    *(float2*)&Op[(warp*32 + i*16 + g    ) * OPP + col] =
                        make_float2(oacc[i][j][0], oacc[i][j][1]);
                    *(float2*)&Op[(warp*32 + i*16 + g + 8) * OPP + col] =
                        make_float2(oacc[i][j][2], oacc[i][j][3]);
                }
        }
        __syncthreads();

        // ---------- reduce partials + LePE + store ----------
        #pragma unroll
        for (int rep = 0; rep < 2; rep++) {
            int idx = tid + 256 * rep;
            int q = idx >> 4;
            int d = idx & 15;
            float o = 0.f;
            #pragma unroll
            for (int w = 0; w < 8; w++) o += Op[(w * 32 + q) * OPP + d];
            int n = qb + q;
            int h = n / WS, w2 = n % WS;
            float lep = bsm[d];
            #pragma unroll
            for (int ky = 0; ky < 3; ky++) {
                int hh = h + ky - 1;
                if (hh < 0 || hh >= HS) continue;
                #pragma unroll
                for (int kx = 0; kx < 3; kx++) {
                    int ww = w2 + kx - 1;
                    if (ww < 0 || ww >= WS) continue;
                    lep = fmaf(wsm[d * 9 + ky * 3 + kx],
                               Qt[d * QP + hh * WS + ww], lep);
                }
            }
            int l = tok_to_l(n, br, wn);
            g_att[((size_t)(b * L_DIM) + l) * C_DIM + cb + d] = o + lep;
        }
        __syncthreads();
    }
}

// ---------------------------------------------------------------------------
__global__ void __launch_bounds__(256) out_transpose_kernel(float* __restrict__ out) {
    __shared__ float sm[128][33];
    int b  = blockIdx.y;
    int l0 = blockIdx.x * 32;
    int tid = threadIdx.x;
    const float* yb = g_y + ((size_t)b * L_DIM + l0) * C_DIM;
    #pragma unroll
    for (int r = 0; r < 16; r++) {
        int i = r * 256 + tid;
        int lloc = i >> 7, c = i & 127;
        sm[c][lloc] = yb[(size_t)lloc * C_DIM + c];
    }
    __syncthreads();
    #pragma unroll
    for (int r = 0; r < 16; r++) {
        int c = r * 8 + (tid >> 5);
        int j = tid & 31;
        out[(size_t)b * C_DIM * L_DIM + (size_t)c * L_DIM + l0 + j] = sm[c][j];
    }
}

// ---------------------------------------------------------------------------
extern "C" void kernel_launch(void* const* d_in, const int* in_sizes, int n_in,
                              void* d_out, int out_size) {
    const float* x       = (const float*)d_in[0];
    const float* z       = (const float*)d_in[1];
    const float* ln1_g   = (const float*)d_in[2];
    const float* ln1_b   = (const float*)d_in[3];
    const float* ln2_g   = (const float*)d_in[4];
    const float* ln2_b   = (const float*)d_in[5];
    const float* Wz1     = (const float*)d_in[6];
    const float* Wz2     = (const float*)d_in[7];
    const float* Wqkv    = (const float*)d_in[8];
    const float* Wproj   = (const float*)d_in[9];
    const float* bproj   = (const float*)d_in[10];
    const float* lepe_w0 = (const float*)d_in[11];
    const float* lepe_b0 = (const float*)d_in[12];
    const float* lepe_w1 = (const float*)d_in[13];
    const float* lepe_b1 = (const float*)d_in[14];
    const float* W1      = (const float*)d_in[15];
    const float* b1      = (const float*)d_in[16];
    const float* W2      = (const float*)d_in[17];
    const float* b2      = (const float*)d_in[18];
    float* out = (float*)d_out;

    float* p_xf;  cudaGetSymbolAddress((void**)&p_xf,  g_xf);
    float* p_h1;  cudaGetSymbolAddress((void**)&p_h1,  g_h1);
    float* p_qkv; cudaGetSymbolAddress((void**)&p_qkv, g_qkv);
    float* p_att; cudaGetSymbolAddress((void**)&p_att, g_att);
    float* p_xf2; cudaGetSymbolAddress((void**)&p_xf2, g_xf2);
    float* p_h2;  cudaGetSymbolAddress((void**)&p_h2,  g_h2);
    float* p_mid; cudaGetSymbolAddress((void**)&p_mid, g_mid);
    float* p_y;   cudaGetSymbolAddress((void**)&p_y,   g_y);

    const int attn_smem = ATTN_SMEM_FLOATS * (int)sizeof(float);
    cudaFuncSetAttribute(attn_kernel, cudaFuncAttributeMaxDynamicSharedMemorySize, attn_smem);

    zproj_kernel<<<8, 256>>>(z, Wz1, Wz2);
    ln1_kernel<<<dim3(128, 8), 256>>>(x, ln1_g, ln1_b);
    gemm_mma_kernel<<<dim3(QKV_N / 128, M_ROWS / 128), 256>>>(
        p_h1, Wqkv, nullptr, nullptr, p_qkv, M_ROWS, QKV_N, C_DIM, 0);
    attn_kernel<<<dim3(64, 4, 2), 256, attn_smem>>>(lepe_w0, lepe_b0, lepe_w1, lepe_b1);
    gemm_mma_kernel<<<dim3(C_DIM / 128, M_ROWS / 128), 256>>>(
        p_att, Wproj, bproj, p_xf, p_xf2, M_ROWS, C_DIM, C_DIM, 0);
    ln2_kernel<<<M_ROWS / 8, 256>>>(ln2_g, ln2_b);
    gemm_mma_kernel<<<dim3(HID / 128, M_ROWS / 128), 256>>>(
        p_h2, W1, b1, nullptr, p_mid, M_ROWS, HID, C_DIM, 1);
    gemm_mma_kernel<<<dim3(C_DIM / 128, M_ROWS / 128), 256>>>(
        p_mid, W2, b2, p_xf2, p_y, M_ROWS, C_DIM, HID, 0);
    out_transpose_kernel<<<dim3(128, 8), 256>>>(out);
}

// round 7
// speedup vs baseline: 4.1227x; 1.3282x over previous
#include <cuda_runtime.h>
#include <cuda_bf16.h>
#include <cuda_fp16.h>
#include <cstdint>
#include <math.h>

// ---------------------------------------------------------------------------
// Problem constants
// ---------------------------------------------------------------------------
#define M_ROWS   32768
#define C_DIM    128
#define L_DIM    4096
#define B_DIM    8
#define HID      512
#define QKV_N    384
#define ZC       512

// ---------------------------------------------------------------------------
// Scratch buffers
// ---------------------------------------------------------------------------
__device__ __align__(16) float g_xf [M_ROWS * C_DIM];
__device__ __align__(16) float g_h1 [M_ROWS * C_DIM];
__device__ __align__(16) float g_qkv[M_ROWS * QKV_N];
__device__ __align__(16) float g_att[M_ROWS * C_DIM];
__device__ __align__(16) float g_xf2[M_ROWS * C_DIM];
__device__ __align__(16) float g_h2 [M_ROWS * C_DIM];
__device__ __align__(16) float g_mid[M_ROWS * HID];
__device__ __align__(16) float g_y  [M_ROWS * C_DIM];
__device__ __align__(16) float g_z1 [B_DIM * C_DIM];
__device__ __align__(16) float g_z2 [B_DIM * C_DIM];

// ---------------------------------------------------------------------------
// helpers
// ---------------------------------------------------------------------------
__device__ __forceinline__ uint32_t pack_h2(float lo, float hi) {
    uint32_t u;                       // first src operand -> upper half
    asm("cvt.rn.f16x2.f32 %0, %1, %2;" : "=r"(u) : "f"(hi), "f"(lo));
    return u;
}
__device__ __forceinline__ float fast_ex2(float x) {
    float y;
    asm("ex2.approx.ftz.f32 %0, %1;" : "=f"(y) : "f"(x));
    return y;
}
__device__ __forceinline__ float gelu_f(float v) {
    return 0.5f * v * (1.f + erff(v * 0.70710678118654752f));
}
__device__ __forceinline__ void mma16n8k16(float* d, const uint32_t* a,
                                           const uint32_t* b) {
    asm("mma.sync.aligned.m16n8k16.row.col.f32.f16.f16.f32 "
        "{%0,%1,%2,%3}, {%4,%5,%6,%7}, {%8,%9}, {%0,%1,%2,%3};"
        : "+f"(d[0]), "+f"(d[1]), "+f"(d[2]), "+f"(d[3])
        : "r"(a[0]), "r"(a[1]), "r"(a[2]), "r"(a[3]), "r"(b[0]), "r"(b[1]));
}

// ---------------------------------------------------------------------------
__global__ void zproj_kernel(const float* __restrict__ z,
                             const float* __restrict__ Wz1,
                             const float* __restrict__ Wz2) {
    int o = blockIdx.x * 256 + threadIdx.x;
    if (o >= 2048) return;
    int which = o >> 10;
    int b = (o >> 7) & 7;
    int c = o & 127;
    const float* W = (which ? Wz2 : Wz1) + c * ZC;
    const float* zb = z + b * ZC;
    float s = 0.f;
    #pragma unroll 8
    for (int k = 0; k < ZC; k++) s += zb[k] * W[k];
    (which ? g_z2 : g_z1)[b * C_DIM + c] = s;
}

// ---------------------------------------------------------------------------
__global__ void __launch_bounds__(256) ln1_kernel(const float* __restrict__ x,
                                                  const float* __restrict__ gamma,
                                                  const float* __restrict__ beta) {
    __shared__ float sm[128][33];
    int b  = blockIdx.y;
    int l0 = blockIdx.x * 32;
    int tid = threadIdx.x;
    const float* xb = x + (size_t)b * C_DIM * L_DIM;
    #pragma unroll
    for (int r = 0; r < 16; r++) {
        int c = r * 8 + (tid >> 5);
        int j = tid & 31;
        sm[c][j] = xb[(size_t)c * L_DIM + l0 + j];
    }
    __syncthreads();
    int warp = tid >> 5, lane = tid & 31;
    #pragma unroll
    for (int rr = 0; rr < 4; rr++) {
        int j = warp + rr * 8;
        float v[4];
        float s = 0.f, s2 = 0.f;
        #pragma unroll
        for (int u = 0; u < 4; u++) {
            v[u] = sm[lane + 32 * u][j];
            s += v[u]; s2 += v[u] * v[u];
        }
        #pragma unroll
        for (int o = 16; o; o >>= 1) {
            s  += __shfl_xor_sync(0xffffffffu, s,  o);
            s2 += __shfl_xor_sync(0xffffffffu, s2, o);
        }
        float mu   = s  * (1.f / 128.f);
        float var  = s2 * (1.f / 128.f) - mu * mu;
        float rstd = rsqrtf(var + 1e-5f);
        int l = l0 + j;
        size_t row = ((size_t)b * L_DIM + l) * C_DIM;
        #pragma unroll
        for (int u = 0; u < 4; u++) {
            int c = lane + 32 * u;
            g_xf[row + c] = v[u];
            g_h1[row + c] = (v[u] - mu) * rstd * gamma[c] + beta[c]
                          + g_z1[b * C_DIM + c];
        }
    }
}

// ---------------------------------------------------------------------------
__global__ void __launch_bounds__(256) ln2_kernel(const float* __restrict__ gamma,
                                                  const float* __restrict__ beta) {
    int row  = blockIdx.x * 8 + (threadIdx.x >> 5);
    int lane = threadIdx.x & 31;
    int b = row >> 12;
    const float* xr = g_xf2 + (size_t)row * C_DIM;
    float v[4]; float s = 0.f, s2 = 0.f;
    #pragma unroll
    for (int u = 0; u < 4; u++) {
        v[u] = xr[lane + 32 * u];
        s += v[u]; s2 += v[u] * v[u];
    }
    #pragma unroll
    for (int o = 16; o; o >>= 1) {
        s  += __shfl_xor_sync(0xffffffffu, s,  o);
        s2 += __shfl_xor_sync(0xffffffffu, s2, o);
    }
    float mu   = s  * (1.f / 128.f);
    float var  = s2 * (1.f / 128.f) - mu * mu;
    float rstd = rsqrtf(var + 1e-5f);
    float* hr = g_h2 + (size_t)row * C_DIM;
    #pragma unroll
    for (int u = 0; u < 4; u++) {
        int c = lane + 32 * u;
        hr[c] = (v[u] - mu) * rstd * gamma[c] + beta[c] + g_z2[b * C_DIM + c];
    }
}

// ---------------------------------------------------------------------------
// Tensor-core GEMM via mma.sync fp16 (m16n8k16, fp32 accumulate):
//   C[m,n] = act( res[m,n] + bias[n] + sum_k A[m,k]*W[n,k] )
// CTA 128x128, BK=16, warp tile 64x32 (2x4 warps).
// smem: half2 packed along k: As/Bs [8 k2-rows][136], stride mod 32 = 8.
// ---------------------------------------------------------------------------
#define GST 136

__global__ void __launch_bounds__(256) gemm_mma_kernel(
        const float* __restrict__ A, const float* __restrict__ W,
        const float* __restrict__ bias, const float* __restrict__ res,
        float* __restrict__ C, int M, int N, int K, int act) {
    __shared__ uint32_t As[8 * GST];
    __shared__ uint32_t Bs[8 * GST];
    int tid  = threadIdx.x;
    int warp = tid >> 5, lane = tid & 31;
    int wm = warp >> 2;
    int wn = warp & 3;
    int t = lane & 3, g = lane >> 2;
    int m0 = blockIdx.y * 128, n0 = blockIdx.x * 128;

    float acc[4][4][4];
    #pragma unroll
    for (int i = 0; i < 4; i++)
        #pragma unroll
        for (int j = 0; j < 4; j++)
            #pragma unroll
            for (int r = 0; r < 4; r++) acc[i][j][r] = 0.f;

    int lrow0 = tid >> 2;               // 0..63
    int lkc   = (tid & 3) << 2;         // 0,4,8,12
    int k2b   = lkc >> 1;               // 0,2,4,6
    float4 pa[2], pb[2];

    #pragma unroll
    for (int r = 0; r < 2; r++) {
        int row = lrow0 + (r << 6);
        pa[r] = *(const float4*)(A + (size_t)(m0 + row) * K + lkc);
        pb[r] = *(const float4*)(W + (size_t)(n0 + row) * K + lkc);
    }

    int slabs = K >> 4;
    for (int s = 0; s < slabs; s++) {
        #pragma unroll
        for (int r = 0; r < 2; r++) {
            int row = lrow0 + (r << 6);
            As[(k2b    ) * GST + row] = pack_h2(pa[r].x, pa[r].y);
            As[(k2b + 1) * GST + row] = pack_h2(pa[r].z, pa[r].w);
            Bs[(k2b    ) * GST + row] = pack_h2(pb[r].x, pb[r].y);
            Bs[(k2b + 1) * GST + row] = pack_h2(pb[r].z, pb[r].w);
        }
        __syncthreads();
        if (s + 1 < slabs) {
            int k0 = (s + 1) << 4;
            #pragma unroll
            for (int r = 0; r < 2; r++) {
                int row = lrow0 + (r << 6);
                pa[r] = *(const float4*)(A + (size_t)(m0 + row) * K + k0 + lkc);
                pb[r] = *(const float4*)(W + (size_t)(n0 + row) * K + k0 + lkc);
            }
        }
        uint32_t af[4][4], bf[4][2];
        #pragma unroll
        for (int i = 0; i < 4; i++) {
            const uint32_t* p = As + t * GST + wm * 64 + i * 16 + g;
            af[i][0] = p[0];
            af[i][1] = p[8];
            af[i][2] = p[4 * GST];
            af[i][3] = p[4 * GST + 8];
        }
        #pragma unroll
        for (int j = 0; j < 4; j++) {
            const uint32_t* p = Bs + t * GST + wn * 32 + j * 8 + g;
            bf[j][0] = p[0];
            bf[j][1] = p[4 * GST];
        }
        #pragma unroll
        for (int i = 0; i < 4; i++)
            #pragma unroll
            for (int j = 0; j < 4; j++)
                mma16n8k16(acc[i][j], af[i], bf[j]);
        __syncthreads();
    }

    #pragma unroll
    for (int i = 0; i < 4; i++) {
        int mr = m0 + wm * 64 + i * 16 + g;
        #pragma unroll
        for (int half = 0; half < 2; half++) {
            int m = mr + 8 * half;
            size_t ro = (size_t)m * N;
            #pragma unroll
            for (int j = 0; j < 4; j++) {
                int n = n0 + wn * 32 + j * 8 + 2 * t;
                float vx = acc[i][j][2 * half];
                float vy = acc[i][j][2 * half + 1];
                if (bias) { vx += bias[n]; vy += bias[n + 1]; }
                if (res) {
                    float2 rv = *(const float2*)(res + ro + n);
                    vx += rv.x; vy += rv.y;
                }
                if (act) { vx = gelu_f(vx); vy = gelu_f(vy); }
                float2 ov = make_float2(vx, vy);
                *(float2*)(C + ro + n) = ov;
            }
        }
    }
}

// ---------------------------------------------------------------------------
// Windowed attention + LePE, fp16 mma (m16n8k16), 2 CTAs/SM.
// smem (uint32 words):
//   Qh[8][520]   half2{d even, d odd} by token       16.6KB
//   Kh[8][520]   same                                 16.6KB
//   Vh[256][24]  half2{key even, key odd} by dim      24.6KB
//   Ss[16][524]  fp32 scores; probs repacked half2 in-place  33.5KB
//   Op[8][16][18] fp32 per-warp PV partials            9.2KB
// 32 passes of 16 queries; 3 syncs per pass.
// ---------------------------------------------------------------------------
#define QP 520
#define VPH 24
#define SP 524
#define OPP 18
#define OFF_QH 0
#define OFF_KH (8*QP)
#define OFF_VH (16*QP)
#define OFF_SS (OFF_VH + 256*VPH)
#define OFF_OP (OFF_SS + 16*SP)
#define OFF_W  (OFF_OP + 8*16*OPP)
#define OFF_B  (OFF_W + 144)
#define ATTN_SMEM_WORDS (OFF_B + 16)
#define SOFTMAX_SC 0.36067376022224085f   // 0.25 * log2(e)

__device__ __forceinline__ int tok_to_l(int n, int br, int wn) {
    if (br == 0) { int h = n >> 3, w = n & 7; return h * 64 + wn * 8 + w; }
    return wn * 512 + n;
}

__global__ void __launch_bounds__(256, 2) attn_kernel(
        const float* __restrict__ lepe_w0, const float* __restrict__ lepe_b0,
        const float* __restrict__ lepe_w1, const float* __restrict__ lepe_b1) {
    extern __shared__ uint32_t smw[];
    uint32_t* Qh  = smw + OFF_QH;
    uint32_t* Kh  = smw + OFF_KH;
    uint32_t* Vh  = smw + OFF_VH;
    float*    Ss  = (float*)(smw + OFF_SS);
    uint32_t* SsU = smw + OFF_SS;
    float*    Op  = (float*)(smw + OFF_OP);
    float*    wsm = (float*)(smw + OFF_W);
    float*    bsm = (float*)(smw + OFF_B);

    int wglob = blockIdx.x;
    int hd    = blockIdx.y;
    int br    = blockIdx.z;
    int b  = wglob >> 3;
    int wn = wglob & 7;
    int cb = br * 64 + hd * 16;
    int tid  = threadIdx.x;
    int warp = tid >> 5, lane = tid & 31;
    int g = lane >> 2, t = lane & 3;

    // ---- load Q,K (half2 along d) and V (half2 along key) ----
    {
        int tp = tid;                       // token pair 0..255
        int t0 = tp * 2, t1 = t0 + 1;
        int l0 = tok_to_l(t0, br, wn), l1 = tok_to_l(t1, br, wn);
        const float* p0 = g_qkv + ((size_t)(b * L_DIM + l0)) * QKV_N + cb;
        const float* p1 = g_qkv + ((size_t)(b * L_DIM + l1)) * QKV_N + cb;
        #pragma unroll
        for (int d4 = 0; d4 < 4; d4++) {
            float4 q0 = ((const float4*)p0)[d4];
            float4 q1 = ((const float4*)p1)[d4];
            Qh[(d4*2    ) * QP + t0] = pack_h2(q0.x, q0.y);
            Qh[(d4*2 + 1) * QP + t0] = pack_h2(q0.z, q0.w);
            Qh[(d4*2    ) * QP + t1] = pack_h2(q1.x, q1.y);
            Qh[(d4*2 + 1) * QP + t1] = pack_h2(q1.z, q1.w);
            float4 k0 = ((const float4*)(p0 + 128))[d4];
            float4 k1 = ((const float4*)(p1 + 128))[d4];
            Kh[(d4*2    ) * QP + t0] = pack_h2(k0.x, k0.y);
            Kh[(d4*2 + 1) * QP + t0] = pack_h2(k0.z, k0.w);
            Kh[(d4*2    ) * QP + t1] = pack_h2(k1.x, k1.y);
            Kh[(d4*2 + 1) * QP + t1] = pack_h2(k1.z, k1.w);
            float4 v0 = ((const float4*)(p0 + 256))[d4];
            float4 v1 = ((const float4*)(p1 + 256))[d4];
            Vh[tp * VPH + d4*4 + 0] = pack_h2(v0.x, v1.x);
            Vh[tp * VPH + d4*4 + 1] = pack_h2(v0.y, v1.y);
            Vh[tp * VPH + d4*4 + 2] = pack_h2(v0.z, v1.z);
            Vh[tp * VPH + d4*4 + 3] = pack_h2(v0.w, v1.w);
        }
    }
    const float* lw = br ? lepe_w1 : lepe_w0;
    const float* lb = br ? lepe_b1 : lepe_b0;
    if (tid < 144) wsm[tid] = lw[hd * 16 * 9 + tid];
    if (tid < 16)  bsm[tid] = lb[hd * 16 + tid];
    __syncthreads();

    const int HS = br ? 8 : 64;
    const int WS = br ? 64 : 8;
    const int kw = warp * 64;               // warp's key slice

    #pragma unroll 1
    for (int pass = 0; pass < 32; pass++) {
        int qb = pass * 16;

        // ---------- phase 1: S = Q K^T (16q x warp's 64k) ----------
        {
            uint32_t af[4];
            af[0] = Qh[t * QP + qb + g];
            af[1] = Qh[t * QP + qb + g + 8];
            af[2] = Qh[(t + 4) * QP + qb + g];
            af[3] = Qh[(t + 4) * QP + qb + g + 8];
            #pragma unroll
            for (int j = 0; j < 8; j++) {
                uint32_t bf[2];
                bf[0] = Kh[t * QP + kw + j * 8 + g];
                bf[1] = Kh[(t + 4) * QP + kw + j * 8 + g];
                float acc[4] = {0.f, 0.f, 0.f, 0.f};
                mma16n8k16(acc, af, bf);
                int col = kw + j * 8 + 2 * t;
                *(float2*)&Ss[g * SP + col]       = make_float2(acc[0], acc[1]);
                *(float2*)&Ss[(g + 8) * SP + col] = make_float2(acc[2], acc[3]);
            }
        }
        __syncthreads();

        // ---------- phase 2: softmax rows + half2 repack in place ----------
        #pragma unroll
        for (int rr = 0; rr < 2; rr++) {
            int row = warp * 2 + rr;
            float* srow = Ss + row * SP;
            float4 v[4];
            #pragma unroll
            for (int j = 0; j < 4; j++)
                v[j] = *(const float4*)(srow + lane * 4 + 128 * j);
            float m = v[0].x;
            #pragma unroll
            for (int j = 0; j < 4; j++) {
                m = fmaxf(m, v[j].x); m = fmaxf(m, v[j].y);
                m = fmaxf(m, v[j].z); m = fmaxf(m, v[j].w);
            }
            #pragma unroll
            for (int o = 16; o; o >>= 1)
                m = fmaxf(m, __shfl_xor_sync(0xffffffffu, m, o));
            float sum = 0.f;
            #pragma unroll
            for (int j = 0; j < 4; j++) {
                v[j].x = fast_ex2((v[j].x - m) * SOFTMAX_SC); sum += v[j].x;
                v[j].y = fast_ex2((v[j].y - m) * SOFTMAX_SC); sum += v[j].y;
                v[j].z = fast_ex2((v[j].z - m) * SOFTMAX_SC); sum += v[j].z;
                v[j].w = fast_ex2((v[j].w - m) * SOFTMAX_SC); sum += v[j].w;
            }
            #pragma unroll
            for (int o = 16; o; o >>= 1)
                sum += __shfl_xor_sync(0xffffffffu, sum, o);
            float inv = 1.f / sum;
            uint32_t* urow = SsU + row * SP;
            #pragma unroll
            for (int j = 0; j < 4; j++) {
                uint2 u;
                u.x = pack_h2(v[j].x * inv, v[j].y * inv);
                u.y = pack_h2(v[j].z * inv, v[j].w * inv);
                *(uint2*)(urow + lane * 2 + 64 * j) = u;
            }
        }
        __syncthreads();

        // ---------- phase 3: O_partial = P V over warp's 64 keys ----------
        {
            float oacc[2][4];
            #pragma unroll
            for (int j = 0; j < 2; j++) {
                oacc[j][0] = 0.f; oacc[j][1] = 0.f;
                oacc[j][2] = 0.f; oacc[j][3] = 0.f;
            }
            #pragma unroll
            for (int ks = 0; ks < 4; ks++) {
                int kh = (kw >> 1) + ks * 8;       // half2 key base
                uint32_t af[4];
                af[0] = SsU[g * SP + kh + t];
                af[1] = SsU[(g + 8) * SP + kh + t];
                af[2] = SsU[g * SP + kh + t + 4];
                af[3] = SsU[(g + 8) * SP + kh + t + 4];
                #pragma unroll
                for (int j = 0; j < 2; j++) {
                    uint32_t bf[2];
                    bf[0] = Vh[(kh + t) * VPH + j * 8 + g];
                    bf[1] = Vh[(kh + t + 4) * VPH + j * 8 + g];
                    mma16n8k16(oacc[j], af, bf);
                }
            }
            #pragma unroll
            for (int j = 0; j < 2; j++) {
                int col = j * 8 + 2 * t;
                *(float2*)&Op[(warp * 16 + g) * OPP + col] =
                    make_float2(oacc[j][0], oacc[j][1]);
                *(float2*)&Op[(warp * 16 + g + 8) * OPP + col] =
                    make_float2(oacc[j][2], oacc[j][3]);
            }
        }
        __syncthreads();

        // ---------- reduce partials + LePE + store (one output/thread) ----
        {
            int q = tid >> 4;               // 0..15
            int d = tid & 15;
            float o = 0.f;
            #pragma unroll
            for (int w = 0; w < 8; w++) o += Op[(w * 16 + q) * OPP + d];
            int n = qb + q;
            int h = n / WS, w2 = n % WS;
            float lep = bsm[d];
            #pragma unroll
            for (int ky = 0; ky < 3; ky++) {
                int hh = h + ky - 1;
                if (hh < 0 || hh >= HS) continue;
                #pragma unroll
                for (int kx = 0; kx < 3; kx++) {
                    int ww = w2 + kx - 1;
                    if (ww < 0 || ww >= WS) continue;
                    uint32_t u = Qh[(d >> 1) * QP + hh * WS + ww];
                    float2 qf = __half22float2(*(__half2*)&u);
                    float qv = (d & 1) ? qf.y : qf.x;
                    lep = fmaf(wsm[d * 9 + ky * 3 + kx], qv, lep);
                }
            }
            int l = tok_to_l(n, br, wn);
            g_att[((size_t)(b * L_DIM) + l) * C_DIM + cb + d] = o + lep;
        }
        // no 4th sync: next phase-1 writes Ss only; its readers finished at
        // the phase-3 sync.  Op is rewritten only after two more syncs.
    }
}

// ---------------------------------------------------------------------------
__global__ void __launch_bounds__(256) out_transpose_kernel(float* __restrict__ out) {
    __shared__ float sm[128][33];
    int b  = blockIdx.y;
    int l0 = blockIdx.x * 32;
    int tid = threadIdx.x;
    const float* yb = g_y + ((size_t)b * L_DIM + l0) * C_DIM;
    #pragma unroll
    for (int r = 0; r < 16; r++) {
        int i = r * 256 + tid;
        int lloc = i >> 7, c = i & 127;
        sm[c][lloc] = yb[(size_t)lloc * C_DIM + c];
    }
    __syncthreads();
    #pragma unroll
    for (int r = 0; r < 16; r++) {
        int c = r * 8 + (tid >> 5);
        int j = tid & 31;
        out[(size_t)b * C_DIM * L_DIM + (size_t)c * L_DIM + l0 + j] = sm[c][j];
    }
}

// ---------------------------------------------------------------------------
extern "C" void kernel_launch(void* const* d_in, const int* in_sizes, int n_in,
                              void* d_out, int out_size) {
    const float* x       = (const float*)d_in[0];
    const float* z       = (const float*)d_in[1];
    const float* ln1_g   = (const float*)d_in[2];
    const float* ln1_b   = (const float*)d_in[3];
    const float* ln2_g   = (const float*)d_in[4];
    const float* ln2_b   = (const float*)d_in[5];
    const float* Wz1     = (const float*)d_in[6];
    const float* Wz2     = (const float*)d_in[7];
    const float* Wqkv    = (const float*)d_in[8];
    const float* Wproj   = (const float*)d_in[9];
    const float* bproj   = (const float*)d_in[10];
    const float* lepe_w0 = (const float*)d_in[11];
    const float* lepe_b0 = (const float*)d_in[12];
    const float* lepe_w1 = (const float*)d_in[13];
    const float* lepe_b1 = (const float*)d_in[14];
    const float* W1      = (const float*)d_in[15];
    const float* b1      = (const float*)d_in[16];
    const float* W2      = (const float*)d_in[17];
    const float* b2      = (const float*)d_in[18];
    float* out = (float*)d_out;

    float* p_xf;  cudaGetSymbolAddress((void**)&p_xf,  g_xf);
    float* p_h1;  cudaGetSymbolAddress((void**)&p_h1,  g_h1);
    float* p_qkv; cudaGetSymbolAddress((void**)&p_qkv, g_qkv);
    float* p_att; cudaGetSymbolAddress((void**)&p_att, g_att);
    float* p_xf2; cudaGetSymbolAddress((void**)&p_xf2, g_xf2);
    float* p_h2;  cudaGetSymbolAddress((void**)&p_h2,  g_h2);
    float* p_mid; cudaGetSymbolAddress((void**)&p_mid, g_mid);
    float* p_y;   cudaGetSymbolAddress((void**)&p_y,   g_y);

    const int attn_smem = ATTN_SMEM_WORDS * (int)sizeof(uint32_t);
    cudaFuncSetAttribute(attn_kernel, cudaFuncAttributeMaxDynamicSharedMemorySize, attn_smem);

    zproj_kernel<<<8, 256>>>(z, Wz1, Wz2);
    ln1_kernel<<<dim3(128, 8), 256>>>(x, ln1_g, ln1_b);
    gemm_mma_kernel<<<dim3(QKV_N / 128, M_ROWS / 128), 256>>>(
        p_h1, Wqkv, nullptr, nullptr, p_qkv, M_ROWS, QKV_N, C_DIM, 0);
    attn_kernel<<<dim3(64, 4, 2), 256, attn_smem>>>(lepe_w0, lepe_b0, lepe_w1, lepe_b1);
    gemm_mma_kernel<<<dim3(C_DIM / 128, M_ROWS / 128), 256>>>(
        p_att, Wproj, bproj, p_xf, p_xf2, M_ROWS, C_DIM, C_DIM, 0);
    ln2_kernel<<<M_ROWS / 8, 256>>>(ln2_g, ln2_b);
    gemm_mma_kernel<<<dim3(HID / 128, M_ROWS / 128), 256>>>(
        p_h2, W1, b1, nullptr, p_mid, M_ROWS, HID, C_DIM, 1);
    gemm_mma_kernel<<<dim3(C_DIM / 128, M_ROWS / 128), 256>>>(
        p_mid, W2, b2, p_xf2, p_y, M_ROWS, C_DIM, HID, 0);
    out_transpose_kernel<<<dim3(128, 8), 256>>>(out);
}

// round 8
// speedup vs baseline: 6.0789x; 1.4745x over previous
#include <cuda_runtime.h>
#include <cuda_bf16.h>
#include <cuda_fp16.h>
#include <cstdint>
#include <math.h>

// ---------------------------------------------------------------------------
// Problem constants
// ---------------------------------------------------------------------------
#define M_ROWS   32768
#define C_DIM    128
#define L_DIM    4096
#define B_DIM    8
#define HID      512
#define QKV_N    384
#define ZC       512

// ---------------------------------------------------------------------------
// Scratch buffers
// ---------------------------------------------------------------------------
__device__ __align__(16) float g_xf [M_ROWS * C_DIM];
__device__ __align__(16) float g_h1 [M_ROWS * C_DIM];
__device__ __align__(16) float g_qkv[M_ROWS * QKV_N];
__device__ __align__(16) float g_att[M_ROWS * C_DIM];
__device__ __align__(16) float g_xf2[M_ROWS * C_DIM];
__device__ __align__(16) float g_h2 [M_ROWS * C_DIM];
__device__ __align__(16) float g_mid[M_ROWS * HID];
__device__ __align__(16) float g_y  [M_ROWS * C_DIM];
__device__ __align__(16) float g_z1 [B_DIM * C_DIM];
__device__ __align__(16) float g_z2 [B_DIM * C_DIM];

// ---------------------------------------------------------------------------
// helpers
// ---------------------------------------------------------------------------
__device__ __forceinline__ uint32_t pack_h2(float lo, float hi) {
    uint32_t u;                       // first src operand -> upper half
    asm("cvt.rn.f16x2.f32 %0, %1, %2;" : "=r"(u) : "f"(hi), "f"(lo));
    return u;
}
__device__ __forceinline__ uint32_t ex2_h2(uint32_t h2) {
    uint32_t r;
    asm("ex2.approx.f16x2 %0, %1;" : "=r"(r) : "r"(h2));
    return r;
}
__device__ __forceinline__ float fast_ex2(float x) {
    float y;
    asm("ex2.approx.ftz.f32 %0, %1;" : "=f"(y) : "f"(x));
    return y;
}
__device__ __forceinline__ float gelu_f(float v) {
    return 0.5f * v * (1.f + erff(v * 0.70710678118654752f));
}
__device__ __forceinline__ void mma16n8k16(float* d, const uint32_t* a,
                                           const uint32_t* b) {
    asm("mma.sync.aligned.m16n8k16.row.col.f32.f16.f16.f32 "
        "{%0,%1,%2,%3}, {%4,%5,%6,%7}, {%8,%9}, {%0,%1,%2,%3};"
        : "+f"(d[0]), "+f"(d[1]), "+f"(d[2]), "+f"(d[3])
        : "r"(a[0]), "r"(a[1]), "r"(a[2]), "r"(a[3]), "r"(b[0]), "r"(b[1]));
}

// ---------------------------------------------------------------------------
__global__ void zproj_kernel(const float* __restrict__ z,
                             const float* __restrict__ Wz1,
                             const float* __restrict__ Wz2) {
    int o = blockIdx.x * 256 + threadIdx.x;
    if (o >= 2048) return;
    int which = o >> 10;
    int b = (o >> 7) & 7;
    int c = o & 127;
    const float* W = (which ? Wz2 : Wz1) + c * ZC;
    const float* zb = z + b * ZC;
    float s = 0.f;
    #pragma unroll 8
    for (int k = 0; k < ZC; k++) s += zb[k] * W[k];
    (which ? g_z2 : g_z1)[b * C_DIM + c] = s;
}

// ---------------------------------------------------------------------------
__global__ void __launch_bounds__(256) ln1_kernel(const float* __restrict__ x,
                                                  const float* __restrict__ gamma,
                                                  const float* __restrict__ beta) {
    __shared__ float sm[128][33];
    int b  = blockIdx.y;
    int l0 = blockIdx.x * 32;
    int tid = threadIdx.x;
    const float* xb = x + (size_t)b * C_DIM * L_DIM;
    #pragma unroll
    for (int r = 0; r < 16; r++) {
        int c = r * 8 + (tid >> 5);
        int j = tid & 31;
        sm[c][j] = xb[(size_t)c * L_DIM + l0 + j];
    }
    __syncthreads();
    int warp = tid >> 5, lane = tid & 31;
    #pragma unroll
    for (int rr = 0; rr < 4; rr++) {
        int j = warp + rr * 8;
        float v[4];
        float s = 0.f, s2 = 0.f;
        #pragma unroll
        for (int u = 0; u < 4; u++) {
            v[u] = sm[lane + 32 * u][j];
            s += v[u]; s2 += v[u] * v[u];
        }
        #pragma unroll
        for (int o = 16; o; o >>= 1) {
            s  += __shfl_xor_sync(0xffffffffu, s,  o);
            s2 += __shfl_xor_sync(0xffffffffu, s2, o);
        }
        float mu   = s  * (1.f / 128.f);
        float var  = s2 * (1.f / 128.f) - mu * mu;
        float rstd = rsqrtf(var + 1e-5f);
        int l = l0 + j;
        size_t row = ((size_t)b * L_DIM + l) * C_DIM;
        #pragma unroll
        for (int u = 0; u < 4; u++) {
            int c = lane + 32 * u;
            g_xf[row + c] = v[u];
            g_h1[row + c] = (v[u] - mu) * rstd * gamma[c] + beta[c]
                          + g_z1[b * C_DIM + c];
        }
    }
}

// ---------------------------------------------------------------------------
__global__ void __launch_bounds__(256) ln2_kernel(const float* __restrict__ gamma,
                                                  const float* __restrict__ beta) {
    int row  = blockIdx.x * 8 + (threadIdx.x >> 5);
    int lane = threadIdx.x & 31;
    int b = row >> 12;
    const float* xr = g_xf2 + (size_t)row * C_DIM;
    float v[4]; float s = 0.f, s2 = 0.f;
    #pragma unroll
    for (int u = 0; u < 4; u++) {
        v[u] = xr[lane + 32 * u];
        s += v[u]; s2 += v[u] * v[u];
    }
    #pragma unroll
    for (int o = 16; o; o >>= 1) {
        s  += __shfl_xor_sync(0xffffffffu, s,  o);
        s2 += __shfl_xor_sync(0xffffffffu, s2, o);
    }
    float mu   = s  * (1.f / 128.f);
    float var  = s2 * (1.f / 128.f) - mu * mu;
    float rstd = rsqrtf(var + 1e-5f);
    float* hr = g_h2 + (size_t)row * C_DIM;
    #pragma unroll
    for (int u = 0; u < 4; u++) {
        int c = lane + 32 * u;
        hr[c] = (v[u] - mu) * rstd * gamma[c] + beta[c] + g_z2[b * C_DIM + c];
    }
}

// ---------------------------------------------------------------------------
// Tensor-core GEMM, fp16 mma m16n8k16, double-buffered smem (1 sync/slab).
// ---------------------------------------------------------------------------
#define GST 136

__global__ void __launch_bounds__(256) gemm_mma_kernel(
        const float* __restrict__ A, const float* __restrict__ W,
        const float* __restrict__ bias, const float* __restrict__ res,
        float* __restrict__ C, int M, int N, int K, int act) {
    __shared__ uint32_t As[2][8 * GST];
    __shared__ uint32_t Bs[2][8 * GST];
    int tid  = threadIdx.x;
    int warp = tid >> 5, lane = tid & 31;
    int wm = warp >> 2;
    int wn = warp & 3;
    int t = lane & 3, g = lane >> 2;
    int m0 = blockIdx.y * 128, n0 = blockIdx.x * 128;

    float acc[4][4][4];
    #pragma unroll
    for (int i = 0; i < 4; i++)
        #pragma unroll
        for (int j = 0; j < 4; j++)
            #pragma unroll
            for (int r = 0; r < 4; r++) acc[i][j][r] = 0.f;

    int lrow0 = tid >> 2;               // 0..63
    int lkc   = (tid & 3) << 2;         // 0,4,8,12
    int k2b   = lkc >> 1;               // 0,2,4,6
    float4 pa[2], pb[2];

    #pragma unroll
    for (int r = 0; r < 2; r++) {
        int row = lrow0 + (r << 6);
        pa[r] = *(const float4*)(A + (size_t)(m0 + row) * K + lkc);
        pb[r] = *(const float4*)(W + (size_t)(n0 + row) * K + lkc);
    }

    int slabs = K >> 4;
    for (int s = 0; s < slabs; s++) {
        uint32_t* Ab = As[s & 1];
        uint32_t* Bb = Bs[s & 1];
        #pragma unroll
        for (int r = 0; r < 2; r++) {
            int row = lrow0 + (r << 6);
            Ab[(k2b    ) * GST + row] = pack_h2(pa[r].x, pa[r].y);
            Ab[(k2b + 1) * GST + row] = pack_h2(pa[r].z, pa[r].w);
            Bb[(k2b    ) * GST + row] = pack_h2(pb[r].x, pb[r].y);
            Bb[(k2b + 1) * GST + row] = pack_h2(pb[r].z, pb[r].w);
        }
        __syncthreads();
        if (s + 1 < slabs) {
            int k0 = (s + 1) << 4;
            #pragma unroll
            for (int r = 0; r < 2; r++) {
                int row = lrow0 + (r << 6);
                pa[r] = *(const float4*)(A + (size_t)(m0 + row) * K + k0 + lkc);
                pb[r] = *(const float4*)(W + (size_t)(n0 + row) * K + k0 + lkc);
            }
        }
        uint32_t af[4][4], bf[4][2];
        #pragma unroll
        for (int i = 0; i < 4; i++) {
            const uint32_t* p = Ab + t * GST + wm * 64 + i * 16 + g;
            af[i][0] = p[0];
            af[i][1] = p[8];
            af[i][2] = p[4 * GST];
            af[i][3] = p[4 * GST + 8];
        }
        #pragma unroll
        for (int j = 0; j < 4; j++) {
            const uint32_t* p = Bb + t * GST + wn * 32 + j * 8 + g;
            bf[j][0] = p[0];
            bf[j][1] = p[4 * GST];
        }
        #pragma unroll
        for (int i = 0; i < 4; i++)
            #pragma unroll
            for (int j = 0; j < 4; j++)
                mma16n8k16(acc[i][j], af[i], bf[j]);
        // no second sync: next store targets the other buffer, and the sync
        // above guarantees everyone finished reading it (mma of slab s-1).
    }

    #pragma unroll
    for (int i = 0; i < 4; i++) {
        int mr = m0 + wm * 64 + i * 16 + g;
        #pragma unroll
        for (int half = 0; half < 2; half++) {
            int m = mr + 8 * half;
            size_t ro = (size_t)m * N;
            #pragma unroll
            for (int j = 0; j < 4; j++) {
                int n = n0 + wn * 32 + j * 8 + 2 * t;
                float vx = acc[i][j][2 * half];
                float vy = acc[i][j][2 * half + 1];
                if (bias) { vx += bias[n]; vy += bias[n + 1]; }
                if (res) {
                    float2 rv = *(const float2*)(res + ro + n);
                    vx += rv.x; vy += rv.y;
                }
                if (act) { vx = gelu_f(vx); vy = gelu_f(vy); }
                float2 ov = make_float2(vx, vy);
                *(float2*)(C + ro + n) = ov;
            }
        }
    }
}

// ---------------------------------------------------------------------------
// Barrier-free flash attention + LePE, fp16 mma.
// Each warp: 16 queries x all 512 keys, online softmax, O in registers.
// smem (uint32 words):
//   Qh[8][520]  half2{2d,2d+1} per token, PRE-SCALED by 0.25*log2e
//   Kh[8][520]  half2 dims, unscaled
//   Vh[256][24] half2{key even,key odd} per dim; dim16 = ones (row-sum trick)
// One __syncthreads after load; none in the main loop.
// ---------------------------------------------------------------------------
#define QP 520
#define VPH 24
#define OFF_QH 0
#define OFF_KH (8*QP)
#define OFF_VH (16*QP)
#define OFF_W  (OFF_VH + 256*VPH)
#define OFF_B  (OFF_W + 144)
#define ATTN_SMEM_WORDS (OFF_B + 16)
#define SOFTMAX_SC 0.36067376022224085f   // 0.25 * log2(e)
#define INV_SC     2.7725887222397811f    // 1 / SOFTMAX_SC = 4 ln 2

__device__ __forceinline__ int tok_to_l(int n, int br, int wn) {
    if (br == 0) { int h = n >> 3, w = n & 7; return h * 64 + wn * 8 + w; }
    return wn * 512 + n;
}

__global__ void __launch_bounds__(256, 2) attn_kernel(
        const float* __restrict__ lepe_w0, const float* __restrict__ lepe_b0,
        const float* __restrict__ lepe_w1, const float* __restrict__ lepe_b1) {
    extern __shared__ uint32_t smw[];
    uint32_t* Qh  = smw + OFF_QH;
    uint32_t* Kh  = smw + OFF_KH;
    uint32_t* Vh  = smw + OFF_VH;
    float*    wsm = (float*)(smw + OFF_W);
    float*    bsm = (float*)(smw + OFF_B);

    int wglob = blockIdx.x;
    int hd    = blockIdx.y;
    int br    = blockIdx.z;
    int b  = wglob >> 3;
    int wn = wglob & 7;
    int cb = br * 64 + hd * 16;
    int tid  = threadIdx.x;
    int warp = tid >> 5, lane = tid & 31;
    int g = lane >> 2, t = lane & 3;

    // ---- load Q (scaled), K, V (+ ones column) ----
    {
        int tp = tid;                       // token pair 0..255
        int t0 = tp * 2, t1 = t0 + 1;
        int l0 = tok_to_l(t0, br, wn), l1 = tok_to_l(t1, br, wn);
        const float* p0 = g_qkv + ((size_t)(b * L_DIM + l0)) * QKV_N + cb;
        const float* p1 = g_qkv + ((size_t)(b * L_DIM + l1)) * QKV_N + cb;
        #pragma unroll
        for (int d4 = 0; d4 < 4; d4++) {
            float4 q0 = ((const float4*)p0)[d4];
            float4 q1 = ((const float4*)p1)[d4];
            Qh[(d4*2    ) * QP + t0] = pack_h2(q0.x * SOFTMAX_SC, q0.y * SOFTMAX_SC);
            Qh[(d4*2 + 1) * QP + t0] = pack_h2(q0.z * SOFTMAX_SC, q0.w * SOFTMAX_SC);
            Qh[(d4*2    ) * QP + t1] = pack_h2(q1.x * SOFTMAX_SC, q1.y * SOFTMAX_SC);
            Qh[(d4*2 + 1) * QP + t1] = pack_h2(q1.z * SOFTMAX_SC, q1.w * SOFTMAX_SC);
            float4 k0 = ((const float4*)(p0 + 128))[d4];
            float4 k1 = ((const float4*)(p1 + 128))[d4];
            Kh[(d4*2    ) * QP + t0] = pack_h2(k0.x, k0.y);
            Kh[(d4*2 + 1) * QP + t0] = pack_h2(k0.z, k0.w);
            Kh[(d4*2    ) * QP + t1] = pack_h2(k1.x, k1.y);
            Kh[(d4*2 + 1) * QP + t1] = pack_h2(k1.z, k1.w);
            float4 v0 = ((const float4*)(p0 + 256))[d4];
            float4 v1 = ((const float4*)(p1 + 256))[d4];
            Vh[tp * VPH + d4*4 + 0] = pack_h2(v0.x, v1.x);
            Vh[tp * VPH + d4*4 + 1] = pack_h2(v0.y, v1.y);
            Vh[tp * VPH + d4*4 + 2] = pack_h2(v0.z, v1.z);
            Vh[tp * VPH + d4*4 + 3] = pack_h2(v0.w, v1.w);
        }
        Vh[tp * VPH + 16] = pack_h2(1.f, 1.f);   // row-sum ones column
        #pragma unroll
        for (int d = 17; d < 24; d++) Vh[tp * VPH + d] = 0u;
    }
    const float* lw = br ? lepe_w1 : lepe_w0;
    const float* lb = br ? lepe_b1 : lepe_b0;
    if (tid < 144) wsm[tid] = lw[hd * 16 * 9 + tid] * INV_SC;  // Q is pre-scaled
    if (tid < 16)  bsm[tid] = lb[hd * 16 + tid];
    __syncthreads();

    const int HS = br ? 8 : 64;
    const int WS = br ? 64 : 8;

    #pragma unroll 1
    for (int pass = 0; pass < 4; pass++) {
        int qb = pass * 128 + warp * 16;

        uint32_t af[4];
        af[0] = Qh[t * QP + qb + g];
        af[1] = Qh[t * QP + qb + g + 8];
        af[2] = Qh[(t + 4) * QP + qb + g];
        af[3] = Qh[(t + 4) * QP + qb + g + 8];

        float m0 = -1e30f, m1 = -1e30f;
        float oacc[3][4];
        #pragma unroll
        for (int j = 0; j < 3; j++) {
            oacc[j][0] = 0.f; oacc[j][1] = 0.f;
            oacc[j][2] = 0.f; oacc[j][3] = 0.f;
        }

        #pragma unroll 1
        for (int c = 0; c < 8; c++) {
            int kb = c * 64;
            // ---- S = Q K^T for this 64-key chunk (scores pre-scaled) ----
            float sacc[8][4];
            #pragma unroll
            for (int j = 0; j < 8; j++) {
                sacc[j][0] = 0.f; sacc[j][1] = 0.f;
                sacc[j][2] = 0.f; sacc[j][3] = 0.f;
                uint32_t bf[2];
                bf[0] = Kh[t * QP + kb + j * 8 + g];
                bf[1] = Kh[(t + 4) * QP + kb + j * 8 + g];
                mma16n8k16(sacc[j], af, bf);
            }
            // ---- online softmax update ----
            float mx0 = sacc[0][0], mx1 = sacc[0][2];
            #pragma unroll
            for (int j = 0; j < 8; j++) {
                mx0 = fmaxf(mx0, fmaxf(sacc[j][0], sacc[j][1]));
                mx1 = fmaxf(mx1, fmaxf(sacc[j][2], sacc[j][3]));
            }
            mx0 = fmaxf(mx0, __shfl_xor_sync(0xffffffffu, mx0, 1));
            mx0 = fmaxf(mx0, __shfl_xor_sync(0xffffffffu, mx0, 2));
            mx1 = fmaxf(mx1, __shfl_xor_sync(0xffffffffu, mx1, 1));
            mx1 = fmaxf(mx1, __shfl_xor_sync(0xffffffffu, mx1, 2));
            float mn0 = fmaxf(m0, mx0), mn1 = fmaxf(m1, mx1);
            float a0 = fast_ex2(m0 - mn0), a1 = fast_ex2(m1 - mn1);
            m0 = mn0; m1 = mn1;
            #pragma unroll
            for (int j = 0; j < 3; j++) {
                oacc[j][0] *= a0; oacc[j][1] *= a0;
                oacc[j][2] *= a1; oacc[j][3] *= a1;
            }
            // ---- P = exp2(S - m) in half2, directly as PV A-fragments ----
            uint32_t pa0[8], pa1[8];
            #pragma unroll
            for (int j = 0; j < 8; j++) {
                pa0[j] = ex2_h2(pack_h2(sacc[j][0] - m0, sacc[j][1] - m0));
                pa1[j] = ex2_h2(pack_h2(sacc[j][2] - m1, sacc[j][3] - m1));
            }
            // ---- O += P V  (3rd n-tile = ones column -> row sums) ----
            #pragma unroll
            for (int ks = 0; ks < 4; ks++) {
                uint32_t pf[4] = { pa0[2*ks], pa1[2*ks], pa0[2*ks+1], pa1[2*ks+1] };
                int kh = c * 32 + ks * 8;
                #pragma unroll
                for (int j = 0; j < 3; j++) {
                    uint32_t bf[2];
                    bf[0] = Vh[(kh + t) * VPH + j * 8 + g];
                    bf[1] = Vh[(kh + t + 4) * VPH + j * 8 + g];
                    mma16n8k16(oacc[j], pf, bf);
                }
            }
        }

        // ---- epilogue: normalize, LePE, store ----
        float l0 = __shfl_sync(0xffffffffu, oacc[2][0], lane & 28);
        float l1 = __shfl_sync(0xffffffffu, oacc[2][2], lane & 28);
        float inv0 = 1.f / l0, inv1 = 1.f / l1;

        #pragma unroll
        for (int half = 0; half < 2; half++) {
            int n = qb + g + 8 * half;
            int hq = n / WS, wq = n % WS;
            float inv = half ? inv1 : inv0;
            int l = tok_to_l(n, br, wn);
            float* orow = g_att + ((size_t)(b * L_DIM) + l) * C_DIM + cb;
            #pragma unroll
            for (int j = 0; j < 2; j++) {
                int d0 = j * 8 + 2 * t;
                float lp0 = bsm[d0], lp1 = bsm[d0 + 1];
                #pragma unroll
                for (int ky = 0; ky < 3; ky++) {
                    int hh = hq + ky - 1;
                    if (hh < 0 || hh >= HS) continue;
                    #pragma unroll
                    for (int kx = 0; kx < 3; kx++) {
                        int ww = wq + kx - 1;
                        if (ww < 0 || ww >= WS) continue;
                        uint32_t u = Qh[(j * 4 + t) * QP + hh * WS + ww];
                        float2 qf = __half22float2(*(__half2*)&u);
                        lp0 = fmaf(wsm[d0 * 9 + ky * 3 + kx], qf.x, lp0);
                        lp1 = fmaf(wsm[(d0 + 1) * 9 + ky * 3 + kx], qf.y, lp1);
                    }
                }
                float v0 = oacc[j][2 * half]     * inv + lp0;
                float v1 = oacc[j][2 * half + 1] * inv + lp1;
                *(float2*)(orow + d0) = make_float2(v0, v1);
            }
        }
    }
}

// ---------------------------------------------------------------------------
__global__ void __launch_bounds__(256) out_transpose_kernel(float* __restrict__ out) {
    __shared__ float sm[128][33];
    int b  = blockIdx.y;
    int l0 = blockIdx.x * 32;
    int tid = threadIdx.x;
    const float* yb = g_y + ((size_t)b * L_DIM + l0) * C_DIM;
    #pragma unroll
    for (int r = 0; r < 16; r++) {
        int i = r * 256 + tid;
        int lloc = i >> 7, c = i & 127;
        sm[c][lloc] = yb[(size_t)lloc * C_DIM + c];
    }
    __syncthreads();
    #pragma unroll
    for (int r = 0; r < 16; r++) {
        int c = r * 8 + (tid >> 5);
        int j = tid & 31;
        out[(size_t)b * C_DIM * L_DIM + (size_t)c * L_DIM + l0 + j] = sm[c][j];
    }
}

// ---------------------------------------------------------------------------
extern "C" void kernel_launch(void* const* d_in, const int* in_sizes, int n_in,
                              void* d_out, int out_size) {
    const float* x       = (const float*)d_in[0];
    const float* z       = (const float*)d_in[1];
    const float* ln1_g   = (const float*)d_in[2];
    const float* ln1_b   = (const float*)d_in[3];
    const float* ln2_g   = (const float*)d_in[4];
    const float* ln2_b   = (const float*)d_in[5];
    const float* Wz1     = (const float*)d_in[6];
    const float* Wz2     = (const float*)d_in[7];
    const float* Wqkv    = (const float*)d_in[8];
    const float* Wproj   = (const float*)d_in[9];
    const float* bproj   = (const float*)d_in[10];
    const float* lepe_w0 = (const float*)d_in[11];
    const float* lepe_b0 = (const float*)d_in[12];
    const float* lepe_w1 = (const float*)d_in[13];
    const float* lepe_b1 = (const float*)d_in[14];
    const float* W1      = (const float*)d_in[15];
    const float* b1      = (const float*)d_in[16];
    const float* W2      = (const float*)d_in[17];
    const float* b2      = (const float*)d_in[18];
    float* out = (float*)d_out;

    float* p_xf;  cudaGetSymbolAddress((void**)&p_xf,  g_xf);
    float* p_h1;  cudaGetSymbolAddress((void**)&p_h1,  g_h1);
    float* p_qkv; cudaGetSymbolAddress((void**)&p_qkv, g_qkv);
    float* p_att; cudaGetSymbolAddress((void**)&p_att, g_att);
    float* p_xf2; cudaGetSymbolAddress((void**)&p_xf2, g_xf2);
    float* p_h2;  cudaGetSymbolAddress((void**)&p_h2,  g_h2);
    float* p_mid; cudaGetSymbolAddress((void**)&p_mid, g_mid);
    float* p_y;   cudaGetSymbolAddress((void**)&p_y,   g_y);

    const int attn_smem = ATTN_SMEM_WORDS * (int)sizeof(uint32_t);
    cudaFuncSetAttribute(attn_kernel, cudaFuncAttributeMaxDynamicSharedMemorySize, attn_smem);

    zproj_kernel<<<8, 256>>>(z, Wz1, Wz2);
    ln1_kernel<<<dim3(128, 8), 256>>>(x, ln1_g, ln1_b);
    gemm_mma_kernel<<<dim3(QKV_N / 128, M_ROWS / 128), 256>>>(
        p_h1, Wqkv, nullptr, nullptr, p_qkv, M_ROWS, QKV_N, C_DIM, 0);
    attn_kernel<<<dim3(64, 4, 2), 256, attn_smem>>>(lepe_w0, lepe_b0, lepe_w1, lepe_b1);
    gemm_mma_kernel<<<dim3(C_DIM / 128, M_ROWS / 128), 256>>>(
        p_att, Wproj, bproj, p_xf, p_xf2, M_ROWS, C_DIM, C_DIM, 0);
    ln2_kernel<<<M_ROWS / 8, 256>>>(ln2_g, ln2_b);
    gemm_mma_kernel<<<dim3(HID / 128, M_ROWS / 128), 256>>>(
        p_h2, W1, b1, nullptr, p_mid, M_ROWS, HID, C_DIM, 1);
    gemm_mma_kernel<<<dim3(C_DIM / 128, M_ROWS / 128), 256>>>(
        p_mid, W2, b2, p_xf2, p_y, M_ROWS, C_DIM, HID, 0);
    out_transpose_kernel<<<dim3(128, 8), 256>>>(out);
}